// round 1
// baseline (speedup 1.0000x reference)
#include <cuda_runtime.h>
#include <math.h>

#define B_ 32
#define D_ 64
#define H_ 8
#define N_ 4096
#define L_ 12
#define DK_ 8
#define NL_ 49152               // N_*L_
#define SCALE 0.3535533905932738f  // 1/sqrt(8)

// ---- scratch (global device arrays; no runtime allocation) ----
__device__ float g_qsm[B_ * D_ * NL_];       // 100663296 floats (402 MB)
__device__ float g_v  [B_ * D_ * NL_];       // 402 MB
__device__ float g_keysm[H_ * L_ * N_ * DK_]; // 3145728 floats
__device__ float g_kv[B_ * H_ * L_ * DK_ * DK_]; // 1572864 floats

// ============================================================
// K0: key_sm = softmax(memory * scale, axis=-1)   [H,L,N,8]
// ============================================================
__global__ void k0_keysm(const float* __restrict__ memin) {
    int i = blockIdx.x * blockDim.x + threadIdx.x;  // row over H*L*N = 393216
    if (i >= H_ * L_ * N_) return;
    const float* p = memin + (size_t)i * 8;
    float v[8];
    float m = -1e30f;
#pragma unroll
    for (int k = 0; k < 8; k++) { v[k] = p[k] * SCALE; m = fmaxf(m, v[k]); }
    float s = 0.f;
#pragma unroll
    for (int k = 0; k < 8; k++) { v[k] = __expf(v[k] - m); s += v[k]; }
    float inv = 1.f / s;
    float* o = g_keysm + (size_t)i * 8;
#pragma unroll
    for (int k = 0; k < 8; k++) o[k] = v[k] * inv;
}

// ============================================================
// K1: q = relu(Wq x + bq); v = relu(Wv x + bv); q_sm = softmax(q*scale per head)
// Block: b fixed, 128 flat positions (n*L+l). 256 thr = 8 ch-groups x 32 lanes,
// each thread: 1 head (8 channels) x 4 positions.
// ============================================================
__global__ __launch_bounds__(256, 2)
void k1_qv(const float* __restrict__ x,  const float* __restrict__ wq,
           const float* __restrict__ bq, const float* __restrict__ wv,
           const float* __restrict__ bv) {
    __shared__ float sWq[64 * 64];
    __shared__ float sWv[64 * 64];
    __shared__ float sX[16][128];

    const int t    = threadIdx.x;
    const int b    = blockIdx.y;
    const int base = blockIdx.x * 128;

    for (int i = t; i < 4096; i += 256) { sWq[i] = wq[i]; sWv[i] = wv[i]; }
    __syncthreads();

    const int lane = t & 31, cg = t >> 5;
    float aq[8][4], av[8][4];
#pragma unroll
    for (int j = 0; j < 8; j++)
#pragma unroll
        for (int i = 0; i < 4; i++) { aq[j][i] = 0.f; av[j][i] = 0.f; }

    const float* xb = x + (size_t)b * D_ * NL_ + base;

    for (int d0 = 0; d0 < 64; d0 += 16) {
        __syncthreads();
        for (int i = t; i < 2048; i += 256)
            sX[i >> 7][i & 127] = xb[(size_t)(d0 + (i >> 7)) * NL_ + (i & 127)];
        __syncthreads();
#pragma unroll
        for (int dd = 0; dd < 16; dd++) {
            const int din = d0 + dd;
            const float x0 = sX[dd][lane],      x1 = sX[dd][lane + 32];
            const float x2 = sX[dd][lane + 64], x3 = sX[dd][lane + 96];
#pragma unroll
            for (int j = 0; j < 8; j++) {
                const float wq_ = sWq[(cg * 8 + j) * 64 + din];
                const float wv_ = sWv[(cg * 8 + j) * 64 + din];
                aq[j][0] += wq_ * x0; aq[j][1] += wq_ * x1;
                aq[j][2] += wq_ * x2; aq[j][3] += wq_ * x3;
                av[j][0] += wv_ * x0; av[j][1] += wv_ * x1;
                av[j][2] += wv_ * x2; av[j][3] += wv_ * x3;
            }
        }
    }

    float bqv[8], bvv[8];
#pragma unroll
    for (int j = 0; j < 8; j++) { bqv[j] = bq[cg * 8 + j]; bvv[j] = bv[cg * 8 + j]; }

#pragma unroll
    for (int i = 0; i < 4; i++) {
        const int pos = base + lane + 32 * i;
        float q[8];
        float m = 0.f;  // relu -> values >= 0, so true max >= 0
#pragma unroll
        for (int j = 0; j < 8; j++) {
            float qq = aq[j][i] + bqv[j];
            qq = qq > 0.f ? qq : 0.f;
            q[j] = qq * SCALE;
            m = fmaxf(m, q[j]);
        }
        float s = 0.f;
#pragma unroll
        for (int j = 0; j < 8; j++) { q[j] = __expf(q[j] - m); s += q[j]; }
        const float inv = 1.f / s;
        const size_t ob = ((size_t)b * 64 + cg * 8) * NL_ + pos;
#pragma unroll
        for (int j = 0; j < 8; j++) {
            g_qsm[ob + (size_t)j * NL_] = q[j] * inv;
            float vv = av[j][i] + bvv[j];
            g_v[ob + (size_t)j * NL_] = vv > 0.f ? vv : 0.f;
        }
    }
}

// ============================================================
// K2: kv[b,h,l,x,y] = sum_n keysm[h,l,n,x] * v[b,h*8+y,n,l]
// Block per (h,b): 192 thr = 12 l-groups x 16 n-phases, reg 8x8 outer products,
// shuffle-reduce over the 16 phases. Deterministic (no atomics).
// ============================================================
#define K2_NCH 32
__global__ __launch_bounds__(192, 3)
void k2_kv() {
    __shared__ float sK[12][8][K2_NCH + 1];  // [l][x][nn]
    __shared__ float sV[8][12][K2_NCH + 1];  // [y][l][nn]

    const int t = threadIdx.x;
    const int h = blockIdx.x;
    const int b = blockIdx.y;
    const int s = t & 15;
    const int l = t >> 4;  // 0..11

    float acc[8][8];
#pragma unroll
    for (int xx = 0; xx < 8; xx++)
#pragma unroll
        for (int yy = 0; yy < 8; yy++) acc[xx][yy] = 0.f;

    for (int n0 = 0; n0 < N_; n0 += K2_NCH) {
        __syncthreads();
        // stage keysm tile: 12*32*8 floats, transpose to [l][x][nn]
        for (int i = t; i < 12 * K2_NCH * 8; i += 192) {
            int ll = i / (K2_NCH * 8);
            int r  = i % (K2_NCH * 8);
            int nn = r >> 3, xx = r & 7;
            sK[ll][xx][nn] =
                g_keysm[((size_t)(h * 12 + ll) * N_ + n0 + nn) * 8 + xx];
        }
        // stage v tile: 8*32*12 floats, transpose to [y][l][nn]
        for (int i = t; i < 8 * K2_NCH * 12; i += 192) {
            int yy = i / (K2_NCH * 12);
            int r  = i % (K2_NCH * 12);
            int nn = r / 12, ll = r % 12;
            sV[yy][ll][nn] =
                g_v[((size_t)b * 64 + h * 8 + yy) * NL_ + (size_t)(n0 + nn) * 12 + ll];
        }
        __syncthreads();

        for (int nn = s; nn < K2_NCH; nn += 16) {
            float kf[8], vf[8];
#pragma unroll
            for (int xx = 0; xx < 8; xx++) kf[xx] = sK[l][xx][nn];
#pragma unroll
            for (int yy = 0; yy < 8; yy++) vf[yy] = sV[yy][l][nn];
#pragma unroll
            for (int xx = 0; xx < 8; xx++)
#pragma unroll
                for (int yy = 0; yy < 8; yy++) acc[xx][yy] += kf[xx] * vf[yy];
        }
    }

    // reduce over the 16 phases: lanes 0..15 / 16..31 each hold one l
#pragma unroll
    for (int xx = 0; xx < 8; xx++)
#pragma unroll
        for (int yy = 0; yy < 8; yy++) {
            float v_ = acc[xx][yy];
            v_ += __shfl_xor_sync(0xffffffffu, v_, 1);
            v_ += __shfl_xor_sync(0xffffffffu, v_, 2);
            v_ += __shfl_xor_sync(0xffffffffu, v_, 4);
            v_ += __shfl_xor_sync(0xffffffffu, v_, 8);
            acc[xx][yy] = v_;
        }
    if (s == 0) {
        float* dst = g_kv + (((size_t)(b * 8 + h) * 12 + l) * 64);
#pragma unroll
        for (int xx = 0; xx < 8; xx++)
#pragma unroll
            for (int yy = 0; yy < 8; yy++) dst[xx * 8 + yy] = acc[xx][yy];
    }
}

// ============================================================
// K3: y = q_sm @ kv + v (row-sum of Aapt == 1 -> attn_dyn = v);
//     yf = relu(Wc y + bc); out = yf*weight + bias + yf
// Same block shape as K1. kv in smem with stride-513 l-padding
// (conflict-free across l-varying lanes).
// ============================================================
__global__ __launch_bounds__(256, 2)
void k3_out(const float* __restrict__ wc, const float* __restrict__ bc,
            const float* __restrict__ weight, const float* __restrict__ bias,
            float* __restrict__ out) {
    extern __shared__ float sm[];
    float* sWc = sm;                  // 4096
    float* sKV = sm + 4096;           // 12*513 = 6156 (index l*513 + h*64 + xy)
    float* sY  = sm + 4096 + 6156;    // 64*128 = 8192

    const int t    = threadIdx.x;
    const int b    = blockIdx.y;
    const int base = blockIdx.x * 128;

    for (int i = t; i < 4096; i += 256) sWc[i] = wc[i];
    for (int i = t; i < 6144; i += 256) {
        int h = i / 768, r = i % 768, l = r >> 6, xy = r & 63;
        sKV[l * 513 + h * 64 + xy] = g_kv[(size_t)b * 6144 + i];
    }
    __syncthreads();

    const int lane = t & 31, cg = t >> 5;

    // phase A: assemble y_pre into sY
#pragma unroll
    for (int i = 0; i < 4; i++) {
        const int pl  = lane + 32 * i;
        const int pos = base + pl;
        const int l   = pos % 12;
        const size_t ib = ((size_t)b * 64 + cg * 8) * NL_ + pos;
        float q[8], v[8];
#pragma unroll
        for (int xx = 0; xx < 8; xx++) q[xx] = g_qsm[ib + (size_t)xx * NL_];
#pragma unroll
        for (int yy = 0; yy < 8; yy++) v[yy] = g_v[ib + (size_t)yy * NL_];
        const float* kvp = sKV + l * 513 + cg * 64;
#pragma unroll
        for (int yy = 0; yy < 8; yy++) {
            float s = v[yy];
#pragma unroll
            for (int xx = 0; xx < 8; xx++) s += q[xx] * kvp[xx * 8 + yy];
            sY[(cg * 8 + yy) * 128 + pl] = s;
        }
    }
    __syncthreads();

    // phase B: Wc GEMV
    float c[8][4];
#pragma unroll
    for (int j = 0; j < 8; j++)
#pragma unroll
        for (int i = 0; i < 4; i++) c[j][i] = 0.f;

#pragma unroll 8
    for (int din = 0; din < 64; din++) {
        const float x0 = sY[din * 128 + lane],      x1 = sY[din * 128 + lane + 32];
        const float x2 = sY[din * 128 + lane + 64], x3 = sY[din * 128 + lane + 96];
#pragma unroll
        for (int j = 0; j < 8; j++) {
            const float w_ = sWc[(cg * 8 + j) * 64 + din];
            c[j][0] += w_ * x0; c[j][1] += w_ * x1;
            c[j][2] += w_ * x2; c[j][3] += w_ * x3;
        }
    }

    // epilogue: relu, out = yf*weight + bias + yf
#pragma unroll
    for (int j = 0; j < 8; j++) {
        const int d = cg * 8 + j;
        const float bcv = bc[d];
        const size_t rowo = (size_t)d * NL_ + base + lane;            // weight/bias
        const size_t outo = ((size_t)b * 64 + d) * NL_ + base + lane; // out
#pragma unroll
        for (int i = 0; i < 4; i++) {
            float yf = c[j][i] + bcv;
            yf = yf > 0.f ? yf : 0.f;
            const float w_ = weight[rowo + 32 * i];
            const float bi = bias[rowo + 32 * i];
            out[outo + 32 * i] = yf * w_ + bi + yf;
        }
    }
}

// ============================================================
extern "C" void kernel_launch(void* const* d_in, const int* in_sizes, int n_in,
                              void* d_out, int out_size) {
    const float* x      = (const float*)d_in[0];
    const float* wq     = (const float*)d_in[1];
    const float* bq     = (const float*)d_in[2];
    const float* wv     = (const float*)d_in[3];
    const float* bv     = (const float*)d_in[4];
    const float* wc     = (const float*)d_in[5];
    const float* bc     = (const float*)d_in[6];
    const float* memin  = (const float*)d_in[7];
    const float* weight = (const float*)d_in[8];
    const float* bias   = (const float*)d_in[9];
    // d_in[10], d_in[11] (nv1, nv2): row-sum of a softmax is identically 1 -> unused.
    float* out = (float*)d_out;

    const int k3_smem = (4096 + 6156 + 8192) * 4;  // 73776 B
    cudaFuncSetAttribute(k3_out, cudaFuncAttributeMaxDynamicSharedMemorySize, k3_smem);

    k0_keysm<<<(H_ * L_ * N_ + 255) / 256, 256>>>(memin);

    dim3 g1(NL_ / 128, B_);
    k1_qv<<<g1, 256>>>(x, wq, bq, wv, bv);

    dim3 g2(H_, B_);
    k2_kv<<<g2, 192>>>();

    dim3 g3(NL_ / 128, B_);
    k3_out<<<g3, 256, k3_smem>>>(wc, bc, weight, bias, out);
}

// round 2
// speedup vs baseline: 1.0546x; 1.0546x over previous
#include <cuda_runtime.h>
#include <cuda_fp16.h>
#include <math.h>

#define B_ 32
#define D_ 64
#define H_ 8
#define N_ 4096
#define L_ 12
#define DK_ 8
#define NL_ 49152               // N_*L_
#define SCALE 0.3535533905932738f  // 1/sqrt(8)

// ---- scratch (global device arrays; no runtime allocation) ----
__device__ __half g_q16[(size_t)B_ * D_ * NL_];   // 201 MB
__device__ __half g_v16[(size_t)B_ * D_ * NL_];   // 201 MB
__device__ float  g_keysm[H_ * L_ * N_ * DK_];
__device__ float  g_kv[B_ * H_ * L_ * DK_ * DK_];

// ============================================================
// K0: key_sm = softmax(memory * scale, axis=-1)   [H,L,N,8]
// ============================================================
__global__ void k0_keysm(const float* __restrict__ memin) {
    int i = blockIdx.x * blockDim.x + threadIdx.x;
    if (i >= H_ * L_ * N_) return;
    const float* p = memin + (size_t)i * 8;
    float v[8];
    float m = -1e30f;
#pragma unroll
    for (int k = 0; k < 8; k++) { v[k] = p[k] * SCALE; m = fmaxf(m, v[k]); }
    float s = 0.f;
#pragma unroll
    for (int k = 0; k < 8; k++) { v[k] = __expf(v[k] - m); s += v[k]; }
    float inv = 1.f / s;
    float* o = g_keysm + (size_t)i * 8;
#pragma unroll
    for (int k = 0; k < 8; k++) o[k] = v[k] * inv;
}

// ============================================================
// K1: q = relu(Wq x + bq); v = relu(Wv x + bv); q_sm = softmax(q*scale/head)
// 256 thr = 8 ch-groups x 32 lanes; thread: 8 out-ch x 4 positions.
// Weights loaded as float4 broadcasts; din register-blocked by 4.
// ============================================================
__global__ __launch_bounds__(256, 2)
void k1_qv(const float* __restrict__ x,  const float* __restrict__ wq,
           const float* __restrict__ bq, const float* __restrict__ wv,
           const float* __restrict__ bv) {
    __shared__ float sWq[64 * 64];
    __shared__ float sWv[64 * 64];
    __shared__ float sX[16][128];

    const int t    = threadIdx.x;
    const int b    = blockIdx.y;
    const int base = blockIdx.x * 128;

    for (int i = t; i < 4096; i += 256) { sWq[i] = wq[i]; sWv[i] = wv[i]; }
    __syncthreads();

    const int lane = t & 31, cg = t >> 5;
    float aq[8][4], av[8][4];
#pragma unroll
    for (int j = 0; j < 8; j++)
#pragma unroll
        for (int i = 0; i < 4; i++) { aq[j][i] = 0.f; av[j][i] = 0.f; }

    const float* xb = x + (size_t)b * D_ * NL_ + base;

    for (int d0 = 0; d0 < 64; d0 += 16) {
        __syncthreads();
        for (int i = t; i < 2048; i += 256)
            sX[i >> 7][i & 127] = xb[(size_t)(d0 + (i >> 7)) * NL_ + (i & 127)];
        __syncthreads();
#pragma unroll 2
        for (int dq = 0; dq < 4; dq++) {        // 4 dins per step
            float xr[4][4];
#pragma unroll
            for (int dd = 0; dd < 4; dd++)
#pragma unroll
                for (int i = 0; i < 4; i++)
                    xr[dd][i] = sX[dq * 4 + dd][lane + 32 * i];
#pragma unroll
            for (int j = 0; j < 8; j++) {
                const int wrow = (cg * 8 + j) * 64 + d0 + dq * 4;
                const float4 wq4 = *(const float4*)&sWq[wrow];
                const float4 wv4 = *(const float4*)&sWv[wrow];
                const float wqa[4] = {wq4.x, wq4.y, wq4.z, wq4.w};
                const float wva[4] = {wv4.x, wv4.y, wv4.z, wv4.w};
#pragma unroll
                for (int dd = 0; dd < 4; dd++)
#pragma unroll
                    for (int i = 0; i < 4; i++) {
                        aq[j][i] += wqa[dd] * xr[dd][i];
                        av[j][i] += wva[dd] * xr[dd][i];
                    }
            }
        }
    }

    float bqv[8], bvv[8];
#pragma unroll
    for (int j = 0; j < 8; j++) { bqv[j] = bq[cg * 8 + j]; bvv[j] = bv[cg * 8 + j]; }

#pragma unroll
    for (int i = 0; i < 4; i++) {
        const int pos = base + lane + 32 * i;
        float q[8];
        float m = 0.f;  // relu -> true max >= 0
#pragma unroll
        for (int j = 0; j < 8; j++) {
            float qq = aq[j][i] + bqv[j];
            qq = qq > 0.f ? qq : 0.f;
            q[j] = qq * SCALE;
            m = fmaxf(m, q[j]);
        }
        float s = 0.f;
#pragma unroll
        for (int j = 0; j < 8; j++) { q[j] = __expf(q[j] - m); s += q[j]; }
        const float inv = 1.f / s;
        const size_t ob = ((size_t)b * 64 + cg * 8) * NL_ + pos;
#pragma unroll
        for (int j = 0; j < 8; j++) {
            g_q16[ob + (size_t)j * NL_] = __float2half_rn(q[j] * inv);
            float vv = av[j][i] + bvv[j];
            g_v16[ob + (size_t)j * NL_] = __float2half_rn(vv > 0.f ? vv : 0.f);
        }
    }
}

// ============================================================
// K2: kv[b,h,l,x,y] = sum_n keysm[h,l,n,x] * v[b,h*8+y,n,l]
// 192 thr = 12 l x 16 n-phases; reg 8x8 outer products; shuffle reduce.
// ============================================================
#define K2_NCH 32
__global__ __launch_bounds__(192, 3)
void k2_kv() {
    __shared__ float sK[12][8][K2_NCH + 1];  // [l][x][nn]
    __shared__ float sV[8][12][K2_NCH + 1];  // [y][l][nn]

    const int t = threadIdx.x;
    const int h = blockIdx.x;
    const int b = blockIdx.y;
    const int s = t & 15;
    const int l = t >> 4;

    float acc[8][8];
#pragma unroll
    for (int xx = 0; xx < 8; xx++)
#pragma unroll
        for (int yy = 0; yy < 8; yy++) acc[xx][yy] = 0.f;

    for (int n0 = 0; n0 < N_; n0 += K2_NCH) {
        __syncthreads();
        for (int i = t; i < 12 * K2_NCH * 8; i += 192) {
            int ll = i / (K2_NCH * 8);
            int r  = i % (K2_NCH * 8);
            int nn = r >> 3, xx = r & 7;
            sK[ll][xx][nn] =
                g_keysm[((size_t)(h * 12 + ll) * N_ + n0 + nn) * 8 + xx];
        }
        for (int i = t; i < 8 * K2_NCH * 12; i += 192) {
            int yy = i / (K2_NCH * 12);
            int r  = i % (K2_NCH * 12);
            int nn = r / 12, ll = r % 12;
            sV[yy][ll][nn] = __half2float(
                g_v16[((size_t)b * 64 + h * 8 + yy) * NL_ + (size_t)(n0 + nn) * 12 + ll]);
        }
        __syncthreads();

        for (int nn = s; nn < K2_NCH; nn += 16) {
            float kf[8], vf[8];
#pragma unroll
            for (int xx = 0; xx < 8; xx++) kf[xx] = sK[l][xx][nn];
#pragma unroll
            for (int yy = 0; yy < 8; yy++) vf[yy] = sV[yy][l][nn];
#pragma unroll
            for (int xx = 0; xx < 8; xx++)
#pragma unroll
                for (int yy = 0; yy < 8; yy++) acc[xx][yy] += kf[xx] * vf[yy];
        }
    }

#pragma unroll
    for (int xx = 0; xx < 8; xx++)
#pragma unroll
        for (int yy = 0; yy < 8; yy++) {
            float v_ = acc[xx][yy];
            v_ += __shfl_xor_sync(0xffffffffu, v_, 1);
            v_ += __shfl_xor_sync(0xffffffffu, v_, 2);
            v_ += __shfl_xor_sync(0xffffffffu, v_, 4);
            v_ += __shfl_xor_sync(0xffffffffu, v_, 8);
            acc[xx][yy] = v_;
        }
    if (s == 0) {
        float* dst = g_kv + (((size_t)(b * 8 + h) * 12 + l) * 64);
#pragma unroll
        for (int xx = 0; xx < 8; xx++)
#pragma unroll
            for (int yy = 0; yy < 8; yy++) dst[xx * 8 + yy] = acc[xx][yy];
    }
}

// ============================================================
// K3: y = q_sm @ kv + v; yf = relu(Wc y + bc); out = yf*weight + bias + yf
// grid.x = b (fast) so 32 batch blocks share weight/bias tiles in L2.
// ============================================================
__global__ __launch_bounds__(256, 2)
void k3_out(const float* __restrict__ wc, const float* __restrict__ bc,
            const float* __restrict__ weight, const float* __restrict__ bias,
            float* __restrict__ out) {
    extern __shared__ float sm[];
    float* sWc = sm;                  // 4096
    float* sKV = sm + 4096;           // 12*513
    float* sY  = sm + 4096 + 6156;    // 64*128

    const int t    = threadIdx.x;
    const int b    = blockIdx.x;
    const int base = blockIdx.y * 128;

    for (int i = t; i < 4096; i += 256) sWc[i] = wc[i];
    for (int i = t; i < 6144; i += 256) {
        int h = i / 768, r = i % 768, l = r >> 6, xy = r & 63;
        sKV[l * 513 + h * 64 + xy] = g_kv[(size_t)b * 6144 + i];
    }
    __syncthreads();

    const int lane = t & 31, cg = t >> 5;

    // phase A: assemble y_pre into sY[din][pos]
#pragma unroll
    for (int i = 0; i < 4; i++) {
        const int pl  = lane + 32 * i;
        const int pos = base + pl;
        const int l   = pos % 12;
        const size_t ib = ((size_t)b * 64 + cg * 8) * NL_ + pos;
        float q[8], v[8];
#pragma unroll
        for (int xx = 0; xx < 8; xx++) q[xx] = __half2float(g_q16[ib + (size_t)xx * NL_]);
#pragma unroll
        for (int yy = 0; yy < 8; yy++) v[yy] = __half2float(g_v16[ib + (size_t)yy * NL_]);
        const float* kvp = sKV + l * 513 + cg * 64;
#pragma unroll
        for (int yy = 0; yy < 8; yy++) {
            float s = v[yy];
#pragma unroll
            for (int xx = 0; xx < 8; xx++) s += q[xx] * kvp[xx * 8 + yy];
            sY[(cg * 8 + yy) * 128 + pl] = s;
        }
    }
    __syncthreads();

    // phase B: Wc GEMV, din blocked by 4, float4 weight broadcasts
    float c[8][4];
#pragma unroll
    for (int j = 0; j < 8; j++)
#pragma unroll
        for (int i = 0; i < 4; i++) c[j][i] = 0.f;

#pragma unroll 2
    for (int dq = 0; dq < 16; dq++) {
        float yr[4][4];
#pragma unroll
        for (int dd = 0; dd < 4; dd++)
#pragma unroll
            for (int i = 0; i < 4; i++)
                yr[dd][i] = sY[(dq * 4 + dd) * 128 + lane + 32 * i];
#pragma unroll
        for (int j = 0; j < 8; j++) {
            const float4 w4 = *(const float4*)&sWc[(cg * 8 + j) * 64 + dq * 4];
            const float wa[4] = {w4.x, w4.y, w4.z, w4.w};
#pragma unroll
            for (int dd = 0; dd < 4; dd++)
#pragma unroll
                for (int i = 0; i < 4; i++)
                    c[j][i] += wa[dd] * yr[dd][i];
        }
    }

    // epilogue
#pragma unroll
    for (int j = 0; j < 8; j++) {
        const int d = cg * 8 + j;
        const float bcv = bc[d];
        const size_t rowo = (size_t)d * NL_ + base + lane;
        const size_t outo = ((size_t)b * 64 + d) * NL_ + base + lane;
#pragma unroll
        for (int i = 0; i < 4; i++) {
            float yf = c[j][i] + bcv;
            yf = yf > 0.f ? yf : 0.f;
            const float w_ = weight[rowo + 32 * i];
            const float bi = bias[rowo + 32 * i];
            out[outo + 32 * i] = yf * w_ + bi + yf;
        }
    }
}

// ============================================================
extern "C" void kernel_launch(void* const* d_in, const int* in_sizes, int n_in,
                              void* d_out, int out_size) {
    const float* x      = (const float*)d_in[0];
    const float* wq     = (const float*)d_in[1];
    const float* bq     = (const float*)d_in[2];
    const float* wv     = (const float*)d_in[3];
    const float* bv     = (const float*)d_in[4];
    const float* wc     = (const float*)d_in[5];
    const float* bc     = (const float*)d_in[6];
    const float* memin  = (const float*)d_in[7];
    const float* weight = (const float*)d_in[8];
    const float* bias   = (const float*)d_in[9];
    // nv1/nv2 unused: row-sum of softmax(…, axis=-1) over that axis == 1.
    float* out = (float*)d_out;

    const int k3_smem = (4096 + 6156 + 8192) * 4;
    cudaFuncSetAttribute(k3_out, cudaFuncAttributeMaxDynamicSharedMemorySize, k3_smem);

    k0_keysm<<<(H_ * L_ * N_ + 255) / 256, 256>>>(memin);

    dim3 g1(NL_ / 128, B_);
    k1_qv<<<g1, 256>>>(x, wq, bq, wv, bv);

    dim3 g2(H_, B_);
    k2_kv<<<g2, 192>>>();

    dim3 g3(B_, NL_ / 128);
    k3_out<<<g3, 256, k3_smem>>>(wc, bc, weight, bias, out);
}

// round 3
// speedup vs baseline: 1.2767x; 1.2106x over previous
#include <cuda_runtime.h>
#include <cuda_fp16.h>
#include <math.h>
#include <stdint.h>

#define B_ 32
#define D_ 64
#define H_ 8
#define N_ 4096
#define L_ 12
#define DK_ 8
#define NL_ 49152
#define SCALE 0.3535533905932738f

// ---- scratch ----
__device__ __half g_q16[(size_t)B_ * D_ * NL_];
__device__ __half g_v16[(size_t)B_ * D_ * NL_];
__device__ float  g_keysm[H_ * L_ * N_ * DK_];
__device__ float  g_kv[B_ * H_ * L_ * DK_ * DK_];

__device__ __forceinline__ void mma16816(float* c, const uint32_t* a,
                                         uint32_t b0, uint32_t b1) {
    asm volatile(
        "mma.sync.aligned.m16n8k16.row.col.f32.f16.f16.f32 "
        "{%0,%1,%2,%3}, {%4,%5,%6,%7}, {%8,%9}, {%0,%1,%2,%3};\n"
        : "+f"(c[0]), "+f"(c[1]), "+f"(c[2]), "+f"(c[3])
        : "r"(a[0]), "r"(a[1]), "r"(a[2]), "r"(a[3]), "r"(b0), "r"(b1));
}

// ============================================================
// K0: key_sm = softmax(memory * scale, axis=-1)
// ============================================================
__global__ void k0_keysm(const float* __restrict__ memin) {
    int i = blockIdx.x * blockDim.x + threadIdx.x;
    if (i >= H_ * L_ * N_) return;
    const float* p = memin + (size_t)i * 8;
    float v[8];
    float m = -1e30f;
#pragma unroll
    for (int k = 0; k < 8; k++) { v[k] = p[k] * SCALE; m = fmaxf(m, v[k]); }
    float s = 0.f;
#pragma unroll
    for (int k = 0; k < 8; k++) { v[k] = __expf(v[k] - m); s += v[k]; }
    float inv = 1.f / s;
    float* o = g_keysm + (size_t)i * 8;
#pragma unroll
    for (int k = 0; k < 8; k++) o[k] = v[k] * inv;
}

// ============================================================
// K1 (HMMA): [q_pre; v_pre](128 x 128pos) = [Wq;Wv](128x64) @ x(64x128pos)
// then relu, per-head softmax(q), store half.
// smem: sW half[128][64] | xs half[128pos][66] | sQV half[128ch][132]
// ============================================================
#define K1_SMEM (16384 + 16896 + 33792)
__global__ __launch_bounds__(256, 2)
void k1_qv(const float* __restrict__ x,  const float* __restrict__ wq,
           const float* __restrict__ bq, const float* __restrict__ wv,
           const float* __restrict__ bv) {
    extern __shared__ char sm1[];
    __half* sW  = (__half*)sm1;                    // 128*64
    __half* xs  = (__half*)(sm1 + 16384);          // 128*66
    __half* sQV = (__half*)(sm1 + 16384 + 16896);  // 128*132

    const int t    = threadIdx.x;
    const int b    = blockIdx.y;
    const int base = blockIdx.x * 128;

    // weights -> half smem (rows 0-63: Wq, 64-127: Wv)
    for (int i = t; i < 4096; i += 256) {
        sW[i]        = __float2half_rn(wq[i]);
        sW[4096 + i] = __float2half_rn(wv[i]);
    }
    // x tile -> half smem, transposed to [pos][din] (pitch 66, conflict-free)
    {
        const int pos = t & 127;
        const int d0  = (t >> 7) * 32;
        const float* xb = x + (size_t)b * D_ * NL_ + base + pos;
        __half* xrow = xs + pos * 66 + d0;
#pragma unroll 8
        for (int dd = 0; dd < 32; dd++)
            xrow[dd] = __float2half_rn(xb[(size_t)(d0 + dd) * NL_]);
    }
    __syncthreads();

    const int wid = t >> 5, lane = t & 31;
    const int g = lane >> 2, q4 = lane & 3;

    // A fragments (warp wid owns out-rows wid*16 .. wid*16+15), K=64 -> 4 k-tiles
    uint32_t a[4][4];
#pragma unroll
    for (int kt = 0; kt < 4; kt++) {
        const __half* wr = sW + kt * 16 + q4 * 2;
        a[kt][0] = *(const uint32_t*)(wr + (wid * 16 + g) * 64);
        a[kt][1] = *(const uint32_t*)(wr + (wid * 16 + g + 8) * 64);
        a[kt][2] = *(const uint32_t*)(wr + (wid * 16 + g) * 64 + 8);
        a[kt][3] = *(const uint32_t*)(wr + (wid * 16 + g + 8) * 64 + 8);
    }

    float acc[16][4];
#pragma unroll
    for (int nt = 0; nt < 16; nt++)
#pragma unroll
        for (int i = 0; i < 4; i++) acc[nt][i] = 0.f;

#pragma unroll
    for (int nt = 0; nt < 16; nt++) {
        const __half* br = xs + (nt * 8 + g) * 66 + q4 * 2;
#pragma unroll
        for (int kt = 0; kt < 4; kt++) {
            uint32_t b0 = *(const uint32_t*)(br + kt * 16);
            uint32_t b1 = *(const uint32_t*)(br + kt * 16 + 8);
            mma16816(acc[nt], a[kt], b0, b1);
        }
    }

    // fragments -> sQV[ch][pos] (half)
#pragma unroll
    for (int nt = 0; nt < 16; nt++) {
        const int col = nt * 8 + q4 * 2;
        *(__half2*)&sQV[(wid * 16 + g) * 132 + col] =
            __floats2half2_rn(acc[nt][0], acc[nt][1]);
        *(__half2*)&sQV[(wid * 16 + g + 8) * 132 + col] =
            __floats2half2_rn(acc[nt][2], acc[nt][3]);
    }
    __syncthreads();

    // epilogue: bias, relu, per-head softmax(q), store
    const int cg = t >> 5;
    float bqv[8], bvv[8];
#pragma unroll
    for (int j = 0; j < 8; j++) { bqv[j] = bq[cg * 8 + j]; bvv[j] = bv[cg * 8 + j]; }

#pragma unroll
    for (int i = 0; i < 4; i++) {
        const int pos = lane + 32 * i;
        float q[8];
        float m = 0.f;
#pragma unroll
        for (int j = 0; j < 8; j++) {
            float qq = __half2float(sQV[(cg * 8 + j) * 132 + pos]) + bqv[j];
            qq = qq > 0.f ? qq : 0.f;
            q[j] = qq * SCALE;
            m = fmaxf(m, q[j]);
        }
        float s = 0.f;
#pragma unroll
        for (int j = 0; j < 8; j++) { q[j] = __expf(q[j] - m); s += q[j]; }
        const float inv = 1.f / s;
        const size_t ob = ((size_t)b * 64 + cg * 8) * NL_ + base + pos;
#pragma unroll
        for (int j = 0; j < 8; j++) {
            g_q16[ob + (size_t)j * NL_] = __float2half_rn(q[j] * inv);
            float vv = __half2float(sQV[(64 + cg * 8 + j) * 132 + pos]) + bvv[j];
            g_v16[ob + (size_t)j * NL_] = __float2half_rn(vv > 0.f ? vv : 0.f);
        }
    }
}

// ============================================================
// K2: kv[b,h,l,x,y] = sum_n keysm[h,l,n,x] * v[b,h*8+y,n,l]
// ============================================================
#define K2_NCH 32
__global__ __launch_bounds__(192, 3)
void k2_kv() {
    __shared__ float sK[12][8][K2_NCH + 1];
    __shared__ float sV[8][12][K2_NCH + 1];

    const int t = threadIdx.x;
    const int h = blockIdx.x;
    const int b = blockIdx.y;
    const int s = t & 15;
    const int l = t >> 4;

    float acc[8][8];
#pragma unroll
    for (int xx = 0; xx < 8; xx++)
#pragma unroll
        for (int yy = 0; yy < 8; yy++) acc[xx][yy] = 0.f;

    for (int n0 = 0; n0 < N_; n0 += K2_NCH) {
        __syncthreads();
        for (int i = t; i < 12 * K2_NCH * 8; i += 192) {
            int ll = i / (K2_NCH * 8);
            int r  = i % (K2_NCH * 8);
            int nn = r >> 3, xx = r & 7;
            sK[ll][xx][nn] =
                g_keysm[((size_t)(h * 12 + ll) * N_ + n0 + nn) * 8 + xx];
        }
        for (int i = t; i < 8 * K2_NCH * 12; i += 192) {
            int yy = i / (K2_NCH * 12);
            int r  = i % (K2_NCH * 12);
            int nn = r / 12, ll = r % 12;
            sV[yy][ll][nn] = __half2float(
                g_v16[((size_t)b * 64 + h * 8 + yy) * NL_ + (size_t)(n0 + nn) * 12 + ll]);
        }
        __syncthreads();

        for (int nn = s; nn < K2_NCH; nn += 16) {
            float kf[8], vf[8];
#pragma unroll
            for (int xx = 0; xx < 8; xx++) kf[xx] = sK[l][xx][nn];
#pragma unroll
            for (int yy = 0; yy < 8; yy++) vf[yy] = sV[yy][l][nn];
#pragma unroll
            for (int xx = 0; xx < 8; xx++)
#pragma unroll
                for (int yy = 0; yy < 8; yy++) acc[xx][yy] += kf[xx] * vf[yy];
        }
    }

#pragma unroll
    for (int xx = 0; xx < 8; xx++)
#pragma unroll
        for (int yy = 0; yy < 8; yy++) {
            float v_ = acc[xx][yy];
            v_ += __shfl_xor_sync(0xffffffffu, v_, 1);
            v_ += __shfl_xor_sync(0xffffffffu, v_, 2);
            v_ += __shfl_xor_sync(0xffffffffu, v_, 4);
            v_ += __shfl_xor_sync(0xffffffffu, v_, 8);
            acc[xx][yy] = v_;
        }
    if (s == 0) {
        float* dst = g_kv + (((size_t)(b * 8 + h) * 12 + l) * 64);
#pragma unroll
        for (int xx = 0; xx < 8; xx++)
#pragma unroll
            for (int yy = 0; yy < 8; yy++) dst[xx * 8 + yy] = acc[xx][yy];
    }
}

// ============================================================
// K3 (HMMA): y = q_sm@kv + v (half, B-layout); yc = Wc @ y (HMMA);
// out = relu(yc+bc)*weight + bias + relu(yc+bc)
// smem: sWc half[64][64] | { sKV f32[12*513] | ys half[128][66] }  overlaid by sO f32[64][132]
// ============================================================
#define K3_SKV_OFF 8192
#define K3_YS_OFF  (8192 + 24624)
#define K3_SMEM    (8192 + 24624 + 16896)
__global__ __launch_bounds__(256, 2)
void k3_out(const float* __restrict__ wc, const float* __restrict__ bc,
            const float* __restrict__ weight, const float* __restrict__ bias,
            float* __restrict__ out) {
    extern __shared__ char sm3[];
    __half* sWc = (__half*)sm3;                    // 64*64
    float*  sKV = (float*)(sm3 + K3_SKV_OFF);      // 12*513
    __half* ys  = (__half*)(sm3 + K3_YS_OFF);      // 128*66
    float*  sO  = (float*)(sm3 + K3_SKV_OFF);      // 64*132 (overlay, after sync)

    const int t    = threadIdx.x;
    const int b    = blockIdx.x;
    const int base = blockIdx.y * 128;

    for (int i = t; i < 4096; i += 256) sWc[i] = __float2half_rn(wc[i]);
    for (int i = t; i < 6144; i += 256) {
        int h = i / 768, r = i % 768, l = r >> 6, xy = r & 63;
        sKV[l * 513 + h * 64 + xy] = g_kv[(size_t)b * 6144 + i];
    }
    __syncthreads();

    const int lane = t & 31, cg = t >> 5;

    // phase A: y[ch][pos] = v + q_sm @ kv  -> ys[pos][ch] (half)
#pragma unroll
    for (int i = 0; i < 4; i++) {
        const int pl  = lane + 32 * i;
        const int pos = base + pl;
        const int l   = pos % 12;
        const size_t ib = ((size_t)b * 64 + cg * 8) * NL_ + pos;
        float q[8], v[8];
#pragma unroll
        for (int xx = 0; xx < 8; xx++) q[xx] = __half2float(g_q16[ib + (size_t)xx * NL_]);
#pragma unroll
        for (int yy = 0; yy < 8; yy++) v[yy] = __half2float(g_v16[ib + (size_t)yy * NL_]);
        const float* kvp = sKV + l * 513 + cg * 64;
        float yv[8];
#pragma unroll
        for (int yy = 0; yy < 8; yy++) {
            float s = v[yy];
#pragma unroll
            for (int xx = 0; xx < 8; xx++) s += q[xx] * kvp[xx * 8 + yy];
            yv[yy] = s;
        }
        __half* yr = ys + pl * 66 + cg * 8;
#pragma unroll
        for (int j = 0; j < 4; j++)
            *(__half2*)(yr + 2 * j) = __floats2half2_rn(yv[2 * j], yv[2 * j + 1]);
    }
    __syncthreads();

    // phase B: HMMA  (M=64 by 4 warp-strips; N=128 split 2 ways)
    const int wid = t >> 5;
    const int g = lane >> 2, q4 = lane & 3;
    const int wm = wid & 3, wn = wid >> 2;

    uint32_t a[4][4];
#pragma unroll
    for (int kt = 0; kt < 4; kt++) {
        const __half* wr = sWc + kt * 16 + q4 * 2;
        a[kt][0] = *(const uint32_t*)(wr + (wm * 16 + g) * 64);
        a[kt][1] = *(const uint32_t*)(wr + (wm * 16 + g + 8) * 64);
        a[kt][2] = *(const uint32_t*)(wr + (wm * 16 + g) * 64 + 8);
        a[kt][3] = *(const uint32_t*)(wr + (wm * 16 + g + 8) * 64 + 8);
    }

    float acc[8][4];
#pragma unroll
    for (int nt = 0; nt < 8; nt++)
#pragma unroll
        for (int i = 0; i < 4; i++) acc[nt][i] = 0.f;

#pragma unroll
    for (int nt = 0; nt < 8; nt++) {
        const __half* br = ys + (wn * 64 + nt * 8 + g) * 66 + q4 * 2;
#pragma unroll
        for (int kt = 0; kt < 4; kt++) {
            uint32_t b0 = *(const uint32_t*)(br + kt * 16);
            uint32_t b1 = *(const uint32_t*)(br + kt * 16 + 8);
            mma16816(acc[nt], a[kt], b0, b1);
        }
    }
    __syncthreads();  // everyone done reading ys/sKV before overlay

    // fragments -> sO[ch][pos] (fp32)
#pragma unroll
    for (int nt = 0; nt < 8; nt++) {
        const int col = wn * 64 + nt * 8 + q4 * 2;
        *(float2*)&sO[(wm * 16 + g) * 132 + col]     = make_float2(acc[nt][0], acc[nt][1]);
        *(float2*)&sO[(wm * 16 + g + 8) * 132 + col] = make_float2(acc[nt][2], acc[nt][3]);
    }
    __syncthreads();

    // epilogue
#pragma unroll
    for (int j = 0; j < 8; j++) {
        const int d = cg * 8 + j;
        const float bcv = bc[d];
        const size_t rowo = (size_t)d * NL_ + base + lane;
        const size_t outo = ((size_t)b * 64 + d) * NL_ + base + lane;
#pragma unroll
        for (int i = 0; i < 4; i++) {
            float yf = sO[d * 132 + lane + 32 * i] + bcv;
            yf = yf > 0.f ? yf : 0.f;
            const float w_ = weight[rowo + 32 * i];
            const float bi = bias[rowo + 32 * i];
            out[outo + 32 * i] = yf * w_ + bi + yf;
        }
    }
}

// ============================================================
extern "C" void kernel_launch(void* const* d_in, const int* in_sizes, int n_in,
                              void* d_out, int out_size) {
    const float* x      = (const float*)d_in[0];
    const float* wq     = (const float*)d_in[1];
    const float* bq     = (const float*)d_in[2];
    const float* wv     = (const float*)d_in[3];
    const float* bv     = (const float*)d_in[4];
    const float* wc     = (const float*)d_in[5];
    const float* bc     = (const float*)d_in[6];
    const float* memin  = (const float*)d_in[7];
    const float* weight = (const float*)d_in[8];
    const float* bias   = (const float*)d_in[9];
    // nv1/nv2 unused: row-sum of softmax == 1 -> attn_dyn = v.
    float* out = (float*)d_out;

    cudaFuncSetAttribute(k1_qv,  cudaFuncAttributeMaxDynamicSharedMemorySize, K1_SMEM);
    cudaFuncSetAttribute(k3_out, cudaFuncAttributeMaxDynamicSharedMemorySize, K3_SMEM);

    k0_keysm<<<(H_ * L_ * N_ + 255) / 256, 256>>>(memin);

    dim3 g1(NL_ / 128, B_);
    k1_qv<<<g1, 256, K1_SMEM>>>(x, wq, bq, wv, bv);

    dim3 g2(H_, B_);
    k2_kv<<<g2, 192>>>();

    dim3 g3(B_, NL_ / 128);
    k3_out<<<g3, 256, K3_SMEM>>>(wc, bc, weight, bias, out);
}

// round 4
// speedup vs baseline: 1.3946x; 1.0923x over previous
#include <cuda_runtime.h>
#include <cuda_fp16.h>
#include <math.h>
#include <stdint.h>

#define B_ 32
#define D_ 64
#define H_ 8
#define N_ 4096
#define L_ 12
#define DK_ 8
#define NL_ 49152
#define SCALE 0.3535533905932738f

// ---- scratch: q_sm & v in [B][NL][64] channel-contiguous half ----
__device__ __half g_q16[(size_t)B_ * NL_ * 64];
__device__ __half g_v16[(size_t)B_ * NL_ * 64];
__device__ float  g_keysm[H_ * L_ * N_ * DK_];
__device__ float  g_kv[B_ * H_ * L_ * DK_ * DK_];

__device__ __forceinline__ void mma16816(float* c, const uint32_t* a,
                                         uint32_t b0, uint32_t b1) {
    asm volatile(
        "mma.sync.aligned.m16n8k16.row.col.f32.f16.f16.f32 "
        "{%0,%1,%2,%3}, {%4,%5,%6,%7}, {%8,%9}, {%0,%1,%2,%3};\n"
        : "+f"(c[0]), "+f"(c[1]), "+f"(c[2]), "+f"(c[3])
        : "r"(a[0]), "r"(a[1]), "r"(a[2]), "r"(a[3]), "r"(b0), "r"(b1));
}

__device__ __forceinline__ uint32_t h2u(__half2 h) {
    return *reinterpret_cast<uint32_t*>(&h);
}

// ============================================================
// K0: key_sm = softmax(memory * scale, axis=-1)
// ============================================================
__global__ void k0_keysm(const float* __restrict__ memin) {
    int i = blockIdx.x * blockDim.x + threadIdx.x;
    if (i >= H_ * L_ * N_) return;
    const float* p = memin + (size_t)i * 8;
    float v[8];
    float m = -1e30f;
#pragma unroll
    for (int k = 0; k < 8; k++) { v[k] = p[k] * SCALE; m = fmaxf(m, v[k]); }
    float s = 0.f;
#pragma unroll
    for (int k = 0; k < 8; k++) { v[k] = __expf(v[k] - m); s += v[k]; }
    float inv = 1.f / s;
    float* o = g_keysm + (size_t)i * 8;
#pragma unroll
    for (int k = 0; k < 8; k++) o[k] = v[k] * inv;
}

// ============================================================
// K1 (HMMA): [q;v](128ch x 128pos) = [Wq;Wv](128x64) @ x(64x128)
// xs pitch 70 (CF stores, <=2-way mma loads). Epilogue: softmax + uint4 stores.
// ============================================================
#define K1_XS_PITCH 70
#define K1_SMEM (16384 + 128 * K1_XS_PITCH * 2 + 128 * 132 * 2)
__global__ __launch_bounds__(256, 2)
void k1_qv(const float* __restrict__ x,  const float* __restrict__ wq,
           const float* __restrict__ bq, const float* __restrict__ wv,
           const float* __restrict__ bv) {
    extern __shared__ char sm1[];
    __half* sW  = (__half*)sm1;                                     // 128*64
    __half* xs  = (__half*)(sm1 + 16384);                           // 128*70
    __half* sQV = (__half*)(sm1 + 16384 + 128 * K1_XS_PITCH * 2);   // 128*132

    const int t    = threadIdx.x;
    const int b    = blockIdx.y;
    const int base = blockIdx.x * 128;

    for (int i = t; i < 4096; i += 256) {
        sW[i]        = __float2half_rn(wq[i]);
        sW[4096 + i] = __float2half_rn(wv[i]);
    }
    {
        const int pos = t & 127;
        const int d0  = (t >> 7) * 32;
        const float* xb = x + (size_t)b * D_ * NL_ + base + pos;
        __half* xrow = xs + pos * K1_XS_PITCH + d0;
#pragma unroll 8
        for (int dd = 0; dd < 32; dd++)
            xrow[dd] = __float2half_rn(xb[(size_t)(d0 + dd) * NL_]);
    }
    __syncthreads();

    const int wid = t >> 5, lane = t & 31;
    const int g = lane >> 2, q4 = lane & 3;

    uint32_t a[4][4];
#pragma unroll
    for (int kt = 0; kt < 4; kt++) {
        const __half* wr = sW + kt * 16 + q4 * 2;
        a[kt][0] = *(const uint32_t*)(wr + (wid * 16 + g) * 64);
        a[kt][1] = *(const uint32_t*)(wr + (wid * 16 + g + 8) * 64);
        a[kt][2] = *(const uint32_t*)(wr + (wid * 16 + g) * 64 + 8);
        a[kt][3] = *(const uint32_t*)(wr + (wid * 16 + g + 8) * 64 + 8);
    }

    float acc[16][4];
#pragma unroll
    for (int nt = 0; nt < 16; nt++)
#pragma unroll
        for (int i = 0; i < 4; i++) acc[nt][i] = 0.f;

#pragma unroll
    for (int nt = 0; nt < 16; nt++) {
        const __half* br = xs + (nt * 8 + g) * K1_XS_PITCH + q4 * 2;
#pragma unroll
        for (int kt = 0; kt < 4; kt++) {
            uint32_t b0 = *(const uint32_t*)(br + kt * 16);
            uint32_t b1 = *(const uint32_t*)(br + kt * 16 + 8);
            mma16816(acc[nt], a[kt], b0, b1);
        }
    }

    // fragments -> sQV[ch][pos] (half, pitch 132)
#pragma unroll
    for (int nt = 0; nt < 16; nt++) {
        const int col = nt * 8 + q4 * 2;
        *(__half2*)&sQV[(wid * 16 + g) * 132 + col] =
            __floats2half2_rn(acc[nt][0], acc[nt][1]);
        *(__half2*)&sQV[(wid * 16 + g + 8) * 132 + col] =
            __floats2half2_rn(acc[nt][2], acc[nt][3]);
    }
    __syncthreads();

    // epilogue: bias+relu, softmax(q) per head, vectorized global stores
    const int cg = t >> 5;
    float bqv[8], bvv[8];
#pragma unroll
    for (int j = 0; j < 8; j++) { bqv[j] = bq[cg * 8 + j]; bvv[j] = bv[cg * 8 + j]; }

#pragma unroll
    for (int i = 0; i < 4; i++) {
        const int pos = lane + 32 * i;
        float q[8];
        float m = 0.f;
#pragma unroll
        for (int j = 0; j < 8; j++) {
            float qq = __half2float(sQV[(cg * 8 + j) * 132 + pos]) + bqv[j];
            qq = qq > 0.f ? qq : 0.f;
            q[j] = qq * SCALE;
            m = fmaxf(m, q[j]);
        }
        float s = 0.f;
#pragma unroll
        for (int j = 0; j < 8; j++) { q[j] = __expf(q[j] - m); s += q[j]; }
        const float inv = 1.f / s;

        uint4 qu, vu;
        qu.x = h2u(__floats2half2_rn(q[0] * inv, q[1] * inv));
        qu.y = h2u(__floats2half2_rn(q[2] * inv, q[3] * inv));
        qu.z = h2u(__floats2half2_rn(q[4] * inv, q[5] * inv));
        qu.w = h2u(__floats2half2_rn(q[6] * inv, q[7] * inv));
        float vv[8];
#pragma unroll
        for (int j = 0; j < 8; j++) {
            float f = __half2float(sQV[(64 + cg * 8 + j) * 132 + pos]) + bvv[j];
            vv[j] = f > 0.f ? f : 0.f;
        }
        vu.x = h2u(__floats2half2_rn(vv[0], vv[1]));
        vu.y = h2u(__floats2half2_rn(vv[2], vv[3]));
        vu.z = h2u(__floats2half2_rn(vv[4], vv[5]));
        vu.w = h2u(__floats2half2_rn(vv[6], vv[7]));

        const size_t ob = ((size_t)b * NL_ + base + pos) * 64 + cg * 8;
        *(uint4*)&g_q16[ob] = qu;
        *(uint4*)&g_v16[ob] = vu;
    }
}

// ============================================================
// K2: kv[b,h,l,x,y] = sum_n keysm[h,l,n,x] * v[b,(n,l),h*8+y]
// v staged as uint4 (8 ch at once), LDS.128 in compute loop.
// ============================================================
#define K2_NCH 32
__global__ __launch_bounds__(192, 3)
void k2_kv() {
    __shared__ float  sK[12][8][K2_NCH + 1];
    __shared__ __half sVh[12][K2_NCH + 1][8];   // [l][nn][y]

    const int t = threadIdx.x;
    const int h = blockIdx.x;
    const int b = blockIdx.y;
    const int s = t & 15;
    const int l = t >> 4;

    float acc[8][8];
#pragma unroll
    for (int xx = 0; xx < 8; xx++)
#pragma unroll
        for (int yy = 0; yy < 8; yy++) acc[xx][yy] = 0.f;

    for (int n0 = 0; n0 < N_; n0 += K2_NCH) {
        __syncthreads();
        for (int i = t; i < 12 * K2_NCH * 8; i += 192) {
            int ll = i / (K2_NCH * 8);
            int r  = i % (K2_NCH * 8);
            int nn = r >> 3, xx = r & 7;
            sK[ll][xx][nn] =
                g_keysm[((size_t)(h * 12 + ll) * N_ + n0 + nn) * 8 + xx];
        }
        for (int i = t; i < 12 * K2_NCH; i += 192) {
            int ll = i % 12, nn = i / 12;
            const int pos = (n0 + nn) * 12 + ll;
            *(uint4*)&sVh[ll][nn][0] =
                *(const uint4*)&g_v16[((size_t)b * NL_ + pos) * 64 + h * 8];
        }
        __syncthreads();

#pragma unroll
        for (int p = 0; p < 2; p++) {
            const int nn = s + 16 * p;
            float kf[8], vf[8];
#pragma unroll
            for (int xx = 0; xx < 8; xx++) kf[xx] = sK[l][xx][nn];
            uint4 vv = *(const uint4*)&sVh[l][nn][0];
            {
                float2 f;
                f = __half22float2(*reinterpret_cast<__half2*>(&vv.x)); vf[0]=f.x; vf[1]=f.y;
                f = __half22float2(*reinterpret_cast<__half2*>(&vv.y)); vf[2]=f.x; vf[3]=f.y;
                f = __half22float2(*reinterpret_cast<__half2*>(&vv.z)); vf[4]=f.x; vf[5]=f.y;
                f = __half22float2(*reinterpret_cast<__half2*>(&vv.w)); vf[6]=f.x; vf[7]=f.y;
            }
#pragma unroll
            for (int xx = 0; xx < 8; xx++)
#pragma unroll
                for (int yy = 0; yy < 8; yy++) acc[xx][yy] += kf[xx] * vf[yy];
        }
    }

#pragma unroll
    for (int xx = 0; xx < 8; xx++)
#pragma unroll
        for (int yy = 0; yy < 8; yy++) {
            float v_ = acc[xx][yy];
            v_ += __shfl_xor_sync(0xffffffffu, v_, 1);
            v_ += __shfl_xor_sync(0xffffffffu, v_, 2);
            v_ += __shfl_xor_sync(0xffffffffu, v_, 4);
            v_ += __shfl_xor_sync(0xffffffffu, v_, 8);
            acc[xx][yy] = v_;
        }
    if (s == 0) {
        float* dst = g_kv + (((size_t)(b * 8 + h) * 12 + l) * 64);
#pragma unroll
        for (int xx = 0; xx < 8; xx++)
#pragma unroll
            for (int yy = 0; yy < 8; yy++) dst[xx * 8 + yy] = acc[xx][yy];
    }
}

// ============================================================
// K3 (HMMA): phase A with LDG.128 q/v + LDS.128 kv; ys pitch 70;
// Wc HMMA; epilogue via sO overlay.
// ============================================================
#define K3_KV_PITCH 516
#define K3_YS_PITCH 70
#define K3_SKV_OFF 8192
#define K3_YS_OFF  (K3_SKV_OFF + 12 * K3_KV_PITCH * 4)        // 8192+24768
#define K3_SMEM    (K3_YS_OFF + 128 * K3_YS_PITCH * 2)        // +17920
__global__ __launch_bounds__(256, 2)
void k3_out(const float* __restrict__ wc, const float* __restrict__ bc,
            const float* __restrict__ weight, const float* __restrict__ bias,
            float* __restrict__ out) {
    extern __shared__ char sm3[];
    __half* sWc = (__half*)sm3;                    // 64*64
    float*  sKV = (float*)(sm3 + K3_SKV_OFF);      // 12*516
    __half* ys  = (__half*)(sm3 + K3_YS_OFF);      // 128*70
    float*  sO  = (float*)(sm3 + K3_SKV_OFF);      // 64*132 overlay

    const int t    = threadIdx.x;
    const int b    = blockIdx.x;
    const int base = blockIdx.y * 128;

    for (int i = t; i < 4096; i += 256) sWc[i] = __float2half_rn(wc[i]);
    for (int i = t; i < 6144; i += 256) {
        int h = i / 768, r = i % 768, l = r >> 6, xy = r & 63;
        sKV[l * K3_KV_PITCH + h * 64 + xy] = g_kv[(size_t)b * 6144 + i];
    }
    __syncthreads();

    const int lane = t & 31, cg = t >> 5;

    // phase A: y = v + q_sm @ kv  -> ys[pos][ch]
#pragma unroll
    for (int i = 0; i < 4; i++) {
        const int pl  = lane + 32 * i;
        const int pos = base + pl;
        const int l   = pos % 12;
        const size_t ib = ((size_t)b * NL_ + pos) * 64 + cg * 8;
        uint4 qr = *(const uint4*)&g_q16[ib];
        uint4 vr = *(const uint4*)&g_v16[ib];
        float q[8], y[8];
        {
            float2 f;
            f = __half22float2(*reinterpret_cast<__half2*>(&qr.x)); q[0]=f.x; q[1]=f.y;
            f = __half22float2(*reinterpret_cast<__half2*>(&qr.y)); q[2]=f.x; q[3]=f.y;
            f = __half22float2(*reinterpret_cast<__half2*>(&qr.z)); q[4]=f.x; q[5]=f.y;
            f = __half22float2(*reinterpret_cast<__half2*>(&qr.w)); q[6]=f.x; q[7]=f.y;
            f = __half22float2(*reinterpret_cast<__half2*>(&vr.x)); y[0]=f.x; y[1]=f.y;
            f = __half22float2(*reinterpret_cast<__half2*>(&vr.y)); y[2]=f.x; y[3]=f.y;
            f = __half22float2(*reinterpret_cast<__half2*>(&vr.z)); y[4]=f.x; y[5]=f.y;
            f = __half22float2(*reinterpret_cast<__half2*>(&vr.w)); y[6]=f.x; y[7]=f.y;
        }
        const float* kvp = sKV + l * K3_KV_PITCH + cg * 64;
#pragma unroll
        for (int xx = 0; xx < 8; xx++) {
            const float4 ka = *(const float4*)(kvp + xx * 8);
            const float4 kb = *(const float4*)(kvp + xx * 8 + 4);
            const float qx = q[xx];
            y[0] += qx * ka.x; y[1] += qx * ka.y; y[2] += qx * ka.z; y[3] += qx * ka.w;
            y[4] += qx * kb.x; y[5] += qx * kb.y; y[6] += qx * kb.z; y[7] += qx * kb.w;
        }
        __half2* yr = (__half2*)(ys + pl * K3_YS_PITCH + cg * 8);
        yr[0] = __floats2half2_rn(y[0], y[1]);
        yr[1] = __floats2half2_rn(y[2], y[3]);
        yr[2] = __floats2half2_rn(y[4], y[5]);
        yr[3] = __floats2half2_rn(y[6], y[7]);
    }
    __syncthreads();

    // phase B: HMMA (M=64 via 4 warp-strips, N=128 split 2 ways)
    const int wid = t >> 5;
    const int g = lane >> 2, q4 = lane & 3;
    const int wm = wid & 3, wn = wid >> 2;

    uint32_t a[4][4];
#pragma unroll
    for (int kt = 0; kt < 4; kt++) {
        const __half* wr = sWc + kt * 16 + q4 * 2;
        a[kt][0] = *(const uint32_t*)(wr + (wm * 16 + g) * 64);
        a[kt][1] = *(const uint32_t*)(wr + (wm * 16 + g + 8) * 64);
        a[kt][2] = *(const uint32_t*)(wr + (wm * 16 + g) * 64 + 8);
        a[kt][3] = *(const uint32_t*)(wr + (wm * 16 + g + 8) * 64 + 8);
    }

    float acc[8][4];
#pragma unroll
    for (int nt = 0; nt < 8; nt++)
#pragma unroll
        for (int i = 0; i < 4; i++) acc[nt][i] = 0.f;

#pragma unroll
    for (int nt = 0; nt < 8; nt++) {
        const __half* br = ys + (wn * 64 + nt * 8 + g) * K3_YS_PITCH + q4 * 2;
#pragma unroll
        for (int kt = 0; kt < 4; kt++) {
            uint32_t b0 = *(const uint32_t*)(br + kt * 16);
            uint32_t b1 = *(const uint32_t*)(br + kt * 16 + 8);
            mma16816(acc[nt], a[kt], b0, b1);
        }
    }
    __syncthreads();

    // fragments -> sO[ch][pos]
#pragma unroll
    for (int nt = 0; nt < 8; nt++) {
        const int col = wn * 64 + nt * 8 + q4 * 2;
        *(float2*)&sO[(wm * 16 + g) * 132 + col]     = make_float2(acc[nt][0], acc[nt][1]);
        *(float2*)&sO[(wm * 16 + g + 8) * 132 + col] = make_float2(acc[nt][2], acc[nt][3]);
    }
    __syncthreads();

    // epilogue
#pragma unroll
    for (int j = 0; j < 8; j++) {
        const int d = cg * 8 + j;
        const float bcv = bc[d];
        const size_t rowo = (size_t)d * NL_ + base + lane;
        const size_t outo = ((size_t)b * 64 + d) * NL_ + base + lane;
#pragma unroll
        for (int i = 0; i < 4; i++) {
            float yf = sO[d * 132 + lane + 32 * i] + bcv;
            yf = yf > 0.f ? yf : 0.f;
            const float w_ = weight[rowo + 32 * i];
            const float bi = bias[rowo + 32 * i];
            out[outo + 32 * i] = yf * w_ + bi + yf;
        }
    }
}

// ============================================================
extern "C" void kernel_launch(void* const* d_in, const int* in_sizes, int n_in,
                              void* d_out, int out_size) {
    const float* x      = (const float*)d_in[0];
    const float* wq     = (const float*)d_in[1];
    const float* bq     = (const float*)d_in[2];
    const float* wv     = (const float*)d_in[3];
    const float* bv     = (const float*)d_in[4];
    const float* wc     = (const float*)d_in[5];
    const float* bc     = (const float*)d_in[6];
    const float* memin  = (const float*)d_in[7];
    const float* weight = (const float*)d_in[8];
    const float* bias   = (const float*)d_in[9];
    // nv1/nv2 unused: row-sum of softmax == 1 -> attn_dyn = v.
    float* out = (float*)d_out;

    cudaFuncSetAttribute(k1_qv,  cudaFuncAttributeMaxDynamicSharedMemorySize, K1_SMEM);
    cudaFuncSetAttribute(k3_out, cudaFuncAttributeMaxDynamicSharedMemorySize, K3_SMEM);

    k0_keysm<<<(H_ * L_ * N_ + 255) / 256, 256>>>(memin);

    dim3 g1(NL_ / 128, B_);
    k1_qv<<<g1, 256, K1_SMEM>>>(x, wq, bq, wv, bv);

    dim3 g2(H_, B_);
    k2_kv<<<g2, 192>>>();

    dim3 g3(B_, NL_ / 128);
    k3_out<<<g3, 256, K3_SMEM>>>(wc, bc, weight, bias, out);
}

// round 6
// speedup vs baseline: 1.8691x; 1.3403x over previous
#include <cuda_runtime.h>
#include <cuda_fp16.h>
#include <math.h>
#include <stdint.h>

#define B_ 32
#define D_ 64
#define H_ 8
#define N_ 4096
#define L_ 12
#define DK_ 8
#define NL_ 49152
#define SCALE 0.3535533905932738f

// ---- scratch ----
__device__ __half g_q16[(size_t)B_ * NL_ * 64];
__device__ __half g_v16[(size_t)B_ * NL_ * 64];
__device__ float  g_keysm[H_ * L_ * N_ * DK_];
__device__ float  g_kv[B_ * H_ * L_ * DK_ * DK_];
__device__ float  g_kvp[4 * B_ * H_ * L_ * DK_ * DK_];

__device__ __forceinline__ void mma16816(float* c, const uint32_t* a,
                                         uint32_t b0, uint32_t b1) {
    asm volatile(
        "mma.sync.aligned.m16n8k16.row.col.f32.f16.f16.f32 "
        "{%0,%1,%2,%3}, {%4,%5,%6,%7}, {%8,%9}, {%0,%1,%2,%3};\n"
        : "+f"(c[0]), "+f"(c[1]), "+f"(c[2]), "+f"(c[3])
        : "r"(a[0]), "r"(a[1]), "r"(a[2]), "r"(a[3]), "r"(b0), "r"(b1));
}

__device__ __forceinline__ uint32_t su(const void* p) {
    return (uint32_t)__cvta_generic_to_shared(p);
}

#define LDSM4(r0, r1, r2, r3, addr)                                        \
    asm volatile("ldmatrix.sync.aligned.m8n8.x4.shared.b16 {%0,%1,%2,%3}, [%4];" \
                 : "=r"(r0), "=r"(r1), "=r"(r2), "=r"(r3) : "r"(addr))

__device__ __forceinline__ uint32_t h2u(__half2 h) {
    return *reinterpret_cast<uint32_t*>(&h);
}

// ============================================================
// K0: key_sm = softmax(memory * scale, axis=-1)
// ============================================================
__global__ void k0_keysm(const float* __restrict__ memin) {
    int i = blockIdx.x * blockDim.x + threadIdx.x;
    if (i >= H_ * L_ * N_) return;
    const float* p = memin + (size_t)i * 8;
    float v[8];
    float m = -1e30f;
#pragma unroll
    for (int k = 0; k < 8; k++) { v[k] = p[k] * SCALE; m = fmaxf(m, v[k]); }
    float s = 0.f;
#pragma unroll
    for (int k = 0; k < 8; k++) { v[k] = __expf(v[k] - m); s += v[k]; }
    float inv = 1.f / s;
    float* o = g_keysm + (size_t)i * 8;
#pragma unroll
    for (int k = 0; k < 8; k++) o[k] = v[k] * inv;
}

// ============================================================
// K1 (HMMA+LDSM): [q;v](128ch x 128pos) = [Wq;Wv](128x64) @ x(64x128)
// ============================================================
#define P72 72
#define K1_XS_OFF  (128 * P72 * 2)
#define K1_SQV_OFF (K1_XS_OFF + 128 * P72 * 2)
#define K1_SMEM    (K1_SQV_OFF + 128 * 132 * 2)
__global__ __launch_bounds__(256, 2)
void k1_qv(const float* __restrict__ x,  const float* __restrict__ wq,
           const float* __restrict__ bq, const float* __restrict__ wv,
           const float* __restrict__ bv) {
    extern __shared__ char sm1[];
    __half* sW  = (__half*)sm1;                    // 128 x 72
    __half* xs  = (__half*)(sm1 + K1_XS_OFF);      // 128 x 72
    __half* sQV = (__half*)(sm1 + K1_SQV_OFF);     // 128 x 132

    const int t    = threadIdx.x;
    const int b    = blockIdx.y;
    const int base = blockIdx.x * 128;

    // weights -> sW (rows 0-63 Wq, 64-127 Wv), 128-bit stores
    for (int i = t; i < 512; i += 256) {
        const int row = i >> 3, seg = i & 7;
        const float4 f0 = *(const float4*)(wq + row * 64 + seg * 8);
        const float4 f1 = *(const float4*)(wq + row * 64 + seg * 8 + 4);
        uint4 u;
        u.x = h2u(__floats2half2_rn(f0.x, f0.y));
        u.y = h2u(__floats2half2_rn(f0.z, f0.w));
        u.z = h2u(__floats2half2_rn(f1.x, f1.y));
        u.w = h2u(__floats2half2_rn(f1.z, f1.w));
        *(uint4*)&sW[row * P72 + seg * 8] = u;
        const float4 g0 = *(const float4*)(wv + row * 64 + seg * 8);
        const float4 g1 = *(const float4*)(wv + row * 64 + seg * 8 + 4);
        u.x = h2u(__floats2half2_rn(g0.x, g0.y));
        u.y = h2u(__floats2half2_rn(g0.z, g0.w));
        u.z = h2u(__floats2half2_rn(g1.x, g1.y));
        u.w = h2u(__floats2half2_rn(g1.z, g1.w));
        *(uint4*)&sW[(64 + row) * P72 + seg * 8] = u;
    }
    // x tile -> xs[pos][din] (transpose), 128-bit stores
    {
        const int pos = t & 127;
        const int d0  = (t >> 7) * 32;
        const float* xb = x + (size_t)b * D_ * NL_ + base + pos;
        uint32_t pk[16];
#pragma unroll 4
        for (int dd = 0; dd < 32; dd += 2) {
            float x0 = xb[(size_t)(d0 + dd) * NL_];
            float x1 = xb[(size_t)(d0 + dd + 1) * NL_];
            pk[dd >> 1] = h2u(__floats2half2_rn(x0, x1));
        }
        uint4* dst = (uint4*)&xs[pos * P72 + d0];
#pragma unroll
        for (int s = 0; s < 4; s++)
            dst[s] = make_uint4(pk[4 * s], pk[4 * s + 1], pk[4 * s + 2], pk[4 * s + 3]);
    }
    __syncthreads();

    const int wid = t >> 5, lane = t & 31;
    const int g = lane >> 2, q4 = lane & 3;

    uint32_t a[4][4];
    {
        const uint32_t abase =
            su(sW + (wid * 16 + (lane & 15)) * P72 + (lane >> 4) * 8);
#pragma unroll
        for (int kt = 0; kt < 4; kt++)
            LDSM4(a[kt][0], a[kt][1], a[kt][2], a[kt][3], abase + kt * 32);
    }

    float acc[16][4];
#pragma unroll
    for (int nt = 0; nt < 16; nt++)
#pragma unroll
        for (int i = 0; i < 4; i++) acc[nt][i] = 0.f;

    const int brow = lane & 7, bseg = lane >> 3;
#pragma unroll
    for (int nt = 0; nt < 16; nt++) {
        const uint32_t bbase = su(xs + (nt * 8 + brow) * P72 + bseg * 8);
#pragma unroll
        for (int kg = 0; kg < 2; kg++) {
            uint32_t r0, r1, r2, r3;
            LDSM4(r0, r1, r2, r3, bbase + kg * 64);
            mma16816(acc[nt], a[kg * 2],     r0, r1);
            mma16816(acc[nt], a[kg * 2 + 1], r2, r3);
        }
    }

    // fragments -> sQV[ch][pos]
#pragma unroll
    for (int nt = 0; nt < 16; nt++) {
        const int col = nt * 8 + q4 * 2;
        *(__half2*)&sQV[(wid * 16 + g) * 132 + col] =
            __floats2half2_rn(acc[nt][0], acc[nt][1]);
        *(__half2*)&sQV[(wid * 16 + g + 8) * 132 + col] =
            __floats2half2_rn(acc[nt][2], acc[nt][3]);
    }
    __syncthreads();

    // epilogue
    const int cg = t >> 5;
    float bqv[8], bvv[8];
#pragma unroll
    for (int j = 0; j < 8; j++) { bqv[j] = bq[cg * 8 + j]; bvv[j] = bv[cg * 8 + j]; }

#pragma unroll
    for (int i = 0; i < 4; i++) {
        const int pos = lane + 32 * i;
        float q[8];
        float m = 0.f;
#pragma unroll
        for (int j = 0; j < 8; j++) {
            float qq = __half2float(sQV[(cg * 8 + j) * 132 + pos]) + bqv[j];
            qq = qq > 0.f ? qq : 0.f;
            q[j] = qq * SCALE;
            m = fmaxf(m, q[j]);
        }
        float s = 0.f;
#pragma unroll
        for (int j = 0; j < 8; j++) { q[j] = __expf(q[j] - m); s += q[j]; }
        const float inv = 1.f / s;

        uint4 qu, vu;
        qu.x = h2u(__floats2half2_rn(q[0] * inv, q[1] * inv));
        qu.y = h2u(__floats2half2_rn(q[2] * inv, q[3] * inv));
        qu.z = h2u(__floats2half2_rn(q[4] * inv, q[5] * inv));
        qu.w = h2u(__floats2half2_rn(q[6] * inv, q[7] * inv));
        float vv[8];
#pragma unroll
        for (int j = 0; j < 8; j++) {
            float f = __half2float(sQV[(64 + cg * 8 + j) * 132 + pos]) + bvv[j];
            vv[j] = f > 0.f ? f : 0.f;
        }
        vu.x = h2u(__floats2half2_rn(vv[0], vv[1]));
        vu.y = h2u(__floats2half2_rn(vv[2], vv[3]));
        vu.z = h2u(__floats2half2_rn(vv[4], vv[5]));
        vu.w = h2u(__floats2half2_rn(vv[6], vv[7]));

        const size_t ob = ((size_t)b * NL_ + base + pos) * 64 + cg * 8;
        *(uint4*)&g_q16[ob] = qu;
        *(uint4*)&g_v16[ob] = vu;
    }
}

// ============================================================
// K2: split-K (4 splits of n) partial kv sums, then reduce.
// ============================================================
#define K2_NCH 32
__global__ __launch_bounds__(192, 3)
void k2_kv() {
    __shared__ float  sK[12][8][K2_NCH + 1];
    __shared__ __half sVh[12][K2_NCH + 1][8];

    const int t = threadIdx.x;
    const int h = blockIdx.x;
    const int b = blockIdx.y;
    const int sp = blockIdx.z;
    const int s = t & 15;
    const int l = t >> 4;

    float acc[8][8];
#pragma unroll
    for (int xx = 0; xx < 8; xx++)
#pragma unroll
        for (int yy = 0; yy < 8; yy++) acc[xx][yy] = 0.f;

    const int nlo = sp * (N_ / 4), nhi = nlo + N_ / 4;
    for (int n0 = nlo; n0 < nhi; n0 += K2_NCH) {
        __syncthreads();
        for (int i = t; i < 12 * K2_NCH * 8; i += 192) {
            int ll = i / (K2_NCH * 8);
            int r  = i % (K2_NCH * 8);
            int nn = r >> 3, xx = r & 7;
            sK[ll][xx][nn] =
                g_keysm[((size_t)(h * 12 + ll) * N_ + n0 + nn) * 8 + xx];
        }
        for (int i = t; i < 12 * K2_NCH; i += 192) {
            int ll = i % 12, nn = i / 12;
            const int pos = (n0 + nn) * 12 + ll;
            *(uint4*)&sVh[ll][nn][0] =
                *(const uint4*)&g_v16[((size_t)b * NL_ + pos) * 64 + h * 8];
        }
        __syncthreads();

#pragma unroll
        for (int p = 0; p < 2; p++) {
            const int nn = s + 16 * p;
            float kf[8], vf[8];
#pragma unroll
            for (int xx = 0; xx < 8; xx++) kf[xx] = sK[l][xx][nn];
            uint4 vv = *(const uint4*)&sVh[l][nn][0];
            {
                float2 f;
                f = __half22float2(*reinterpret_cast<__half2*>(&vv.x)); vf[0]=f.x; vf[1]=f.y;
                f = __half22float2(*reinterpret_cast<__half2*>(&vv.y)); vf[2]=f.x; vf[3]=f.y;
                f = __half22float2(*reinterpret_cast<__half2*>(&vv.z)); vf[4]=f.x; vf[5]=f.y;
                f = __half22float2(*reinterpret_cast<__half2*>(&vv.w)); vf[6]=f.x; vf[7]=f.y;
            }
#pragma unroll
            for (int xx = 0; xx < 8; xx++)
#pragma unroll
                for (int yy = 0; yy < 8; yy++) acc[xx][yy] += kf[xx] * vf[yy];
        }
    }

#pragma unroll
    for (int xx = 0; xx < 8; xx++)
#pragma unroll
        for (int yy = 0; yy < 8; yy++) {
            float v_ = acc[xx][yy];
            v_ += __shfl_xor_sync(0xffffffffu, v_, 1);
            v_ += __shfl_xor_sync(0xffffffffu, v_, 2);
            v_ += __shfl_xor_sync(0xffffffffu, v_, 4);
            v_ += __shfl_xor_sync(0xffffffffu, v_, 8);
            acc[xx][yy] = v_;
        }
    if (s == 0) {
        float* dst = g_kvp + (size_t)sp * (B_ * H_ * L_ * 64) +
                     (((size_t)(b * 8 + h) * 12 + l) * 64);
#pragma unroll
        for (int xx = 0; xx < 8; xx++)
#pragma unroll
            for (int yy = 0; yy < 8; yy++) dst[xx * 8 + yy] = acc[xx][yy];
    }
}

__global__ void k2r_reduce() {
    const int i = blockIdx.x * 256 + threadIdx.x;
    const int S = B_ * H_ * L_ * 64;
    if (i >= S) return;
    g_kv[i] = g_kvp[i] + g_kvp[i + S] + g_kvp[i + 2 * S] + g_kvp[i + 3 * S];
}

// ============================================================
// K3 (HMMA+LDSM): y = q_sm@kv + v; yc = Wc@y; direct-fragment epilogue.
// ============================================================
#define KVH_PITCH 552
#define K3_KVH_OFF (64 * P72 * 2)                       // 9216
#define K3_YS_OFF  (K3_KVH_OFF + 12 * KVH_PITCH * 2)    // 9216+13248
#define K3_SMEM    (K3_YS_OFF + 128 * P72 * 2)
__global__ __launch_bounds__(256, 2)
void k3_out(const float* __restrict__ wc, const float* __restrict__ bc,
            const float* __restrict__ weight, const float* __restrict__ bias,
            float* __restrict__ out) {
    extern __shared__ char sm3[];
    __half* sWc = (__half*)sm3;                    // 64 x 72
    __half* kvh = (__half*)(sm3 + K3_KVH_OFF);     // 12 x 552
    __half* ys  = (__half*)(sm3 + K3_YS_OFF);      // 128 x 72

    const int t    = threadIdx.x;
    const int b    = blockIdx.x;
    const int base = blockIdx.y * 128;

    // Wc -> sWc (pitch 72), 128-bit stores
    for (int i = t; i < 512; i += 256) {
        const int row = i >> 3, seg = i & 7;
        const float4 f0 = *(const float4*)(wc + row * 64 + seg * 8);
        const float4 f1 = *(const float4*)(wc + row * 64 + seg * 8 + 4);
        uint4 u;
        u.x = h2u(__floats2half2_rn(f0.x, f0.y));
        u.y = h2u(__floats2half2_rn(f0.z, f0.w));
        u.z = h2u(__floats2half2_rn(f1.x, f1.y));
        u.w = h2u(__floats2half2_rn(f1.z, f1.w));
        *(uint4*)&sWc[row * P72 + seg * 8] = u;
    }
    // kv -> kvh half [l][h*64 + xy]  (g_kv is (h*12+l)*64 + xy: h-major!)
    for (int i = t; i < 3072; i += 256) {
        const int idx = i * 2;
        const float2 f = *(const float2*)(g_kv + (size_t)b * 6144 + idx);
        const int h = idx / 768, r = idx % 768, l = r >> 6, xy = r & 63;
        *(__half2*)&kvh[l * KVH_PITCH + h * 64 + xy] = __floats2half2_rn(f.x, f.y);
    }
    __syncthreads();

    const int lane = t & 31, cg = t >> 5;

    // phase A: y = v + q_sm @ kv  -> ys[pos][ch]
#pragma unroll
    for (int i = 0; i < 4; i++) {
        const int pl  = lane + 32 * i;
        const int pos = base + pl;
        const int l   = pos % 12;
        const size_t ib = ((size_t)b * NL_ + pos) * 64 + cg * 8;
        uint4 qr = *(const uint4*)&g_q16[ib];
        uint4 vr = *(const uint4*)&g_v16[ib];
        float q[8], y[8];
        {
            float2 f;
            f = __half22float2(*reinterpret_cast<__half2*>(&qr.x)); q[0]=f.x; q[1]=f.y;
            f = __half22float2(*reinterpret_cast<__half2*>(&qr.y)); q[2]=f.x; q[3]=f.y;
            f = __half22float2(*reinterpret_cast<__half2*>(&qr.z)); q[4]=f.x; q[5]=f.y;
            f = __half22float2(*reinterpret_cast<__half2*>(&qr.w)); q[6]=f.x; q[7]=f.y;
            f = __half22float2(*reinterpret_cast<__half2*>(&vr.x)); y[0]=f.x; y[1]=f.y;
            f = __half22float2(*reinterpret_cast<__half2*>(&vr.y)); y[2]=f.x; y[3]=f.y;
            f = __half22float2(*reinterpret_cast<__half2*>(&vr.z)); y[4]=f.x; y[5]=f.y;
            f = __half22float2(*reinterpret_cast<__half2*>(&vr.w)); y[6]=f.x; y[7]=f.y;
        }
        const __half* kvp = kvh + l * KVH_PITCH + cg * 64;
#pragma unroll
        for (int xx = 0; xx < 8; xx++) {
            uint4 kk = *(const uint4*)(kvp + xx * 8);
            const float qx = q[xx];
            float2 f;
            f = __half22float2(*reinterpret_cast<__half2*>(&kk.x));
            y[0] += qx * f.x; y[1] += qx * f.y;
            f = __half22float2(*reinterpret_cast<__half2*>(&kk.y));
            y[2] += qx * f.x; y[3] += qx * f.y;
            f = __half22float2(*reinterpret_cast<__half2*>(&kk.z));
            y[4] += qx * f.x; y[5] += qx * f.y;
            f = __half22float2(*reinterpret_cast<__half2*>(&kk.w));
            y[6] += qx * f.x; y[7] += qx * f.y;
        }
        uint4 u;
        u.x = h2u(__floats2half2_rn(y[0], y[1]));
        u.y = h2u(__floats2half2_rn(y[2], y[3]));
        u.z = h2u(__floats2half2_rn(y[4], y[5]));
        u.w = h2u(__floats2half2_rn(y[6], y[7]));
        *(uint4*)&ys[pl * P72 + cg * 8] = u;
    }
    __syncthreads();

    // phase B: HMMA via LDSM (warps: 4 m-strips x 2 n-halves)
    const int wid = t >> 5;
    const int g = lane >> 2, q4 = lane & 3;
    const int wm = wid & 3, wn = wid >> 2;

    uint32_t a[4][4];
    {
        const uint32_t abase =
            su(sWc + (wm * 16 + (lane & 15)) * P72 + (lane >> 4) * 8);
#pragma unroll
        for (int kt = 0; kt < 4; kt++)
            LDSM4(a[kt][0], a[kt][1], a[kt][2], a[kt][3], abase + kt * 32);
    }

    float acc[8][4];
#pragma unroll
    for (int nt = 0; nt < 8; nt++)
#pragma unroll
        for (int i = 0; i < 4; i++) acc[nt][i] = 0.f;

    const int brow = lane & 7, bseg = lane >> 3;
#pragma unroll
    for (int nt = 0; nt < 8; nt++) {
        const uint32_t bbase =
            su(ys + (wn * 64 + nt * 8 + brow) * P72 + bseg * 8);
#pragma unroll
        for (int kg = 0; kg < 2; kg++) {
            uint32_t r0, r1, r2, r3;
            LDSM4(r0, r1, r2, r3, bbase + kg * 64);
            mma16816(acc[nt], a[kg * 2],     r0, r1);
            mma16816(acc[nt], a[kg * 2 + 1], r2, r3);
        }
    }

    // direct-fragment epilogue
    const int r0 = wm * 16 + g, r1 = r0 + 8;
    const float bc0 = bc[r0], bc1 = bc[r1];
#pragma unroll
    for (int nt = 0; nt < 8; nt++) {
        const int col = base + wn * 64 + nt * 8 + q4 * 2;
        const size_t w0 = (size_t)r0 * NL_ + col;
        const size_t w1 = (size_t)r1 * NL_ + col;
        const float2 wg0 = *(const float2*)(weight + w0);
        const float2 wg1 = *(const float2*)(weight + w1);
        const float2 bi0 = *(const float2*)(bias + w0);
        const float2 bi1 = *(const float2*)(bias + w1);
        float yf;
        float2 o0, o1;
        yf = acc[nt][0] + bc0; yf = yf > 0.f ? yf : 0.f;
        o0.x = yf * wg0.x + bi0.x + yf;
        yf = acc[nt][1] + bc0; yf = yf > 0.f ? yf : 0.f;
        o0.y = yf * wg0.y + bi0.y + yf;
        yf = acc[nt][2] + bc1; yf = yf > 0.f ? yf : 0.f;
        o1.x = yf * wg1.x + bi1.x + yf;
        yf = acc[nt][3] + bc1; yf = yf > 0.f ? yf : 0.f;
        o1.y = yf * wg1.y + bi1.y + yf;
        *(float2*)(out + ((size_t)b * 64) * NL_ + w0) = o0;
        *(float2*)(out + ((size_t)b * 64) * NL_ + w1) = o1;
    }
}

// ============================================================
extern "C" void kernel_launch(void* const* d_in, const int* in_sizes, int n_in,
                              void* d_out, int out_size) {
    const float* x      = (const float*)d_in[0];
    const float* wq     = (const float*)d_in[1];
    const float* bq     = (const float*)d_in[2];
    const float* wv     = (const float*)d_in[3];
    const float* bv     = (const float*)d_in[4];
    const float* wc     = (const float*)d_in[5];
    const float* bc     = (const float*)d_in[6];
    const float* memin  = (const float*)d_in[7];
    const float* weight = (const float*)d_in[8];
    const float* bias   = (const float*)d_in[9];
    // nv1/nv2 unused: row-sum of softmax == 1 -> attn_dyn = v.
    float* out = (float*)d_out;

    cudaFuncSetAttribute(k1_qv,  cudaFuncAttributeMaxDynamicSharedMemorySize, K1_SMEM);
    cudaFuncSetAttribute(k3_out, cudaFuncAttributeMaxDynamicSharedMemorySize, K3_SMEM);

    k0_keysm<<<(H_ * L_ * N_ + 255) / 256, 256>>>(memin);

    dim3 g1(NL_ / 128, B_);
    k1_qv<<<g1, 256, K1_SMEM>>>(x, wq, bq, wv, bv);

    dim3 g2(H_, B_, 4);
    k2_kv<<<g2, 192>>>();
    k2r_reduce<<<(B_ * H_ * L_ * 64 + 255) / 256, 256>>>();

    dim3 g3(B_, NL_ / 128);
    k3_out<<<g3, 256, K3_SMEM>>>(wc, bc, weight, bias, out);
}

// round 7
// speedup vs baseline: 2.4776x; 1.3255x over previous
#include <cuda_runtime.h>
#include <cuda_fp16.h>
#include <math.h>
#include <stdint.h>

#define B_ 32
#define D_ 64
#define H_ 8
#define N_ 4096
#define L_ 12
#define DK_ 8
#define NL_ 49152
#define SCALE 0.3535533905932738f

// ---- scratch ----
__device__ __half g_q16[(size_t)B_ * NL_ * 64];
__device__ __half g_v16[(size_t)B_ * NL_ * 64];
__device__ __half g_keysm16[(size_t)H_ * L_ * N_ * DK_];
__device__ float  g_kv[B_ * H_ * L_ * DK_ * DK_];
__device__ float  g_kvp[4 * B_ * H_ * L_ * DK_ * DK_];

__device__ __forceinline__ void mma16816(float* c, const uint32_t* a,
                                         uint32_t b0, uint32_t b1) {
    asm volatile(
        "mma.sync.aligned.m16n8k16.row.col.f32.f16.f16.f32 "
        "{%0,%1,%2,%3}, {%4,%5,%6,%7}, {%8,%9}, {%0,%1,%2,%3};\n"
        : "+f"(c[0]), "+f"(c[1]), "+f"(c[2]), "+f"(c[3])
        : "r"(a[0]), "r"(a[1]), "r"(a[2]), "r"(a[3]), "r"(b0), "r"(b1));
}

__device__ __forceinline__ uint32_t su(const void* p) {
    return (uint32_t)__cvta_generic_to_shared(p);
}

#define LDSM4(r0, r1, r2, r3, addr)                                        \
    asm volatile("ldmatrix.sync.aligned.m8n8.x4.shared.b16 {%0,%1,%2,%3}, [%4];" \
                 : "=r"(r0), "=r"(r1), "=r"(r2), "=r"(r3) : "r"(addr))

__device__ __forceinline__ uint32_t h2u(__half2 h) {
    return *reinterpret_cast<uint32_t*>(&h);
}

// ============================================================
// K0: key_sm = softmax(memory * scale, axis=-1) -> fp16
// ============================================================
__global__ void k0_keysm(const float* __restrict__ memin) {
    int i = blockIdx.x * blockDim.x + threadIdx.x;
    if (i >= H_ * L_ * N_) return;
    const float4 f0 = ((const float4*)memin)[(size_t)i * 2];
    const float4 f1 = ((const float4*)memin)[(size_t)i * 2 + 1];
    float v[8] = {f0.x, f0.y, f0.z, f0.w, f1.x, f1.y, f1.z, f1.w};
    float m = -1e30f;
#pragma unroll
    for (int k = 0; k < 8; k++) { v[k] *= SCALE; m = fmaxf(m, v[k]); }
    float s = 0.f;
#pragma unroll
    for (int k = 0; k < 8; k++) { v[k] = __expf(v[k] - m); s += v[k]; }
    const float inv = 1.f / s;
    uint4 u;
    u.x = h2u(__floats2half2_rn(v[0] * inv, v[1] * inv));
    u.y = h2u(__floats2half2_rn(v[2] * inv, v[3] * inv));
    u.z = h2u(__floats2half2_rn(v[4] * inv, v[5] * inv));
    u.w = h2u(__floats2half2_rn(v[6] * inv, v[7] * inv));
    ((uint4*)g_keysm16)[i] = u;
}

// ============================================================
// K1 (HMMA+LDSM, two-pass acc): [q;v](128 x 128) = [Wq;Wv] @ x
// ============================================================
#define P72 72
#define K1_XS_OFF  (128 * P72 * 2)
#define K1_SQV_OFF (K1_XS_OFF + 128 * P72 * 2)
#define K1_SMEM    (K1_SQV_OFF + 128 * 132 * 2)
__global__ __launch_bounds__(256, 3)
void k1_qv(const float* __restrict__ x,  const float* __restrict__ wq,
           const float* __restrict__ bq, const float* __restrict__ wv,
           const float* __restrict__ bv) {
    extern __shared__ char sm1[];
    __half* sW  = (__half*)sm1;                    // 128 x 72
    __half* xs  = (__half*)(sm1 + K1_XS_OFF);      // 128 x 72
    __half* sQV = (__half*)(sm1 + K1_SQV_OFF);     // 128 x 132

    const int t    = threadIdx.x;
    const int b    = blockIdx.y;
    const int base = blockIdx.x * 128;

    for (int i = t; i < 512; i += 256) {
        const int row = i >> 3, seg = i & 7;
        const float4 f0 = *(const float4*)(wq + row * 64 + seg * 8);
        const float4 f1 = *(const float4*)(wq + row * 64 + seg * 8 + 4);
        uint4 u;
        u.x = h2u(__floats2half2_rn(f0.x, f0.y));
        u.y = h2u(__floats2half2_rn(f0.z, f0.w));
        u.z = h2u(__floats2half2_rn(f1.x, f1.y));
        u.w = h2u(__floats2half2_rn(f1.z, f1.w));
        *(uint4*)&sW[row * P72 + seg * 8] = u;
        const float4 g0 = *(const float4*)(wv + row * 64 + seg * 8);
        const float4 g1 = *(const float4*)(wv + row * 64 + seg * 8 + 4);
        u.x = h2u(__floats2half2_rn(g0.x, g0.y));
        u.y = h2u(__floats2half2_rn(g0.z, g0.w));
        u.z = h2u(__floats2half2_rn(g1.x, g1.y));
        u.w = h2u(__floats2half2_rn(g1.z, g1.w));
        *(uint4*)&sW[(64 + row) * P72 + seg * 8] = u;
    }
    {
        const int pos = t & 127;
        const int d0  = (t >> 7) * 32;
        const float* xb = x + (size_t)b * D_ * NL_ + base + pos;
        uint32_t pk[16];
#pragma unroll 4
        for (int dd = 0; dd < 32; dd += 2) {
            float x0 = xb[(size_t)(d0 + dd) * NL_];
            float x1 = xb[(size_t)(d0 + dd + 1) * NL_];
            pk[dd >> 1] = h2u(__floats2half2_rn(x0, x1));
        }
        uint4* dst = (uint4*)&xs[pos * P72 + d0];
#pragma unroll
        for (int s = 0; s < 4; s++)
            dst[s] = make_uint4(pk[4 * s], pk[4 * s + 1], pk[4 * s + 2], pk[4 * s + 3]);
    }
    __syncthreads();

    const int wid = t >> 5, lane = t & 31;
    const int g = lane >> 2, q4 = lane & 3;

    uint32_t a[4][4];
    {
        const uint32_t abase =
            su(sW + (wid * 16 + (lane & 15)) * P72 + (lane >> 4) * 8);
#pragma unroll
        for (int kt = 0; kt < 4; kt++)
            LDSM4(a[kt][0], a[kt][1], a[kt][2], a[kt][3], abase + kt * 32);
    }

    const int brow = lane & 7, bseg = lane >> 3;
#pragma unroll
    for (int pass = 0; pass < 2; pass++) {
        float acc[8][4];
#pragma unroll
        for (int nt = 0; nt < 8; nt++)
#pragma unroll
            for (int i = 0; i < 4; i++) acc[nt][i] = 0.f;

#pragma unroll
        for (int nt = 0; nt < 8; nt++) {
            const int ntg = pass * 8 + nt;
            const uint32_t bbase = su(xs + (ntg * 8 + brow) * P72 + bseg * 8);
#pragma unroll
            for (int kg = 0; kg < 2; kg++) {
                uint32_t r0, r1, r2, r3;
                LDSM4(r0, r1, r2, r3, bbase + kg * 64);
                mma16816(acc[nt], a[kg * 2],     r0, r1);
                mma16816(acc[nt], a[kg * 2 + 1], r2, r3);
            }
        }
#pragma unroll
        for (int nt = 0; nt < 8; nt++) {
            const int col = (pass * 8 + nt) * 8 + q4 * 2;
            *(__half2*)&sQV[(wid * 16 + g) * 132 + col] =
                __floats2half2_rn(acc[nt][0], acc[nt][1]);
            *(__half2*)&sQV[(wid * 16 + g + 8) * 132 + col] =
                __floats2half2_rn(acc[nt][2], acc[nt][3]);
        }
    }
    __syncthreads();

    // epilogue
    const int cg = t >> 5;
    float bqv[8], bvv[8];
#pragma unroll
    for (int j = 0; j < 8; j++) { bqv[j] = bq[cg * 8 + j]; bvv[j] = bv[cg * 8 + j]; }

#pragma unroll
    for (int i = 0; i < 4; i++) {
        const int pos = lane + 32 * i;
        float q[8];
        float m = 0.f;
#pragma unroll
        for (int j = 0; j < 8; j++) {
            float qq = __half2float(sQV[(cg * 8 + j) * 132 + pos]) + bqv[j];
            qq = qq > 0.f ? qq : 0.f;
            q[j] = qq * SCALE;
            m = fmaxf(m, q[j]);
        }
        float s = 0.f;
#pragma unroll
        for (int j = 0; j < 8; j++) { q[j] = __expf(q[j] - m); s += q[j]; }
        const float inv = 1.f / s;

        uint4 qu, vu;
        qu.x = h2u(__floats2half2_rn(q[0] * inv, q[1] * inv));
        qu.y = h2u(__floats2half2_rn(q[2] * inv, q[3] * inv));
        qu.z = h2u(__floats2half2_rn(q[4] * inv, q[5] * inv));
        qu.w = h2u(__floats2half2_rn(q[6] * inv, q[7] * inv));
        float vv[8];
#pragma unroll
        for (int j = 0; j < 8; j++) {
            float f = __half2float(sQV[(64 + cg * 8 + j) * 132 + pos]) + bvv[j];
            vv[j] = f > 0.f ? f : 0.f;
        }
        vu.x = h2u(__floats2half2_rn(vv[0], vv[1]));
        vu.y = h2u(__floats2half2_rn(vv[2], vv[3]));
        vu.z = h2u(__floats2half2_rn(vv[4], vv[5]));
        vu.w = h2u(__floats2half2_rn(vv[6], vv[7]));

        const size_t ob = ((size_t)b * NL_ + base + pos) * 64 + cg * 8;
        *(uint4*)&g_q16[ob] = qu;
        *(uint4*)&g_v16[ob] = vu;
    }
}

// ============================================================
// K2: split-K partial kv sums; fp16 tiles staged as uint4.
// ============================================================
#define K2_NCH 64
__global__ __launch_bounds__(192, 3)
void k2_kv() {
    __shared__ __half sK[12][K2_NCH][8];
    __shared__ __half sV[12][K2_NCH][8];

    const int t = threadIdx.x;
    const int h = blockIdx.x;
    const int b = blockIdx.y;
    const int sp = blockIdx.z;
    const int s = t & 15;
    const int l = t >> 4;

    float acc[8][8];
#pragma unroll
    for (int xx = 0; xx < 8; xx++)
#pragma unroll
        for (int yy = 0; yy < 8; yy++) acc[xx][yy] = 0.f;

    const int nlo = sp * (N_ / 4), nhi = nlo + N_ / 4;
    for (int n0 = nlo; n0 < nhi; n0 += K2_NCH) {
        __syncthreads();
#pragma unroll
        for (int i = t; i < 12 * K2_NCH; i += 192) {
            const int ll = i >> 6, nn = i & 63;
            *(uint4*)&sK[ll][nn][0] =
                *(const uint4*)&g_keysm16[((size_t)(h * 12 + ll) * N_ + n0 + nn) * 8];
        }
#pragma unroll
        for (int i = t; i < 12 * K2_NCH; i += 192) {
            const int ll = i % 12, nn = i / 12;
            const int pos = (n0 + nn) * 12 + ll;
            *(uint4*)&sV[ll][nn][0] =
                *(const uint4*)&g_v16[((size_t)b * NL_ + pos) * 64 + h * 8];
        }
        __syncthreads();

#pragma unroll
        for (int p = 0; p < 4; p++) {
            const int nn = s + 16 * p;
            float kf[8], vf[8];
            uint4 ku = *(const uint4*)&sK[l][nn][0];
            uint4 vu = *(const uint4*)&sV[l][nn][0];
            {
                float2 f;
                f = __half22float2(*reinterpret_cast<__half2*>(&ku.x)); kf[0]=f.x; kf[1]=f.y;
                f = __half22float2(*reinterpret_cast<__half2*>(&ku.y)); kf[2]=f.x; kf[3]=f.y;
                f = __half22float2(*reinterpret_cast<__half2*>(&ku.z)); kf[4]=f.x; kf[5]=f.y;
                f = __half22float2(*reinterpret_cast<__half2*>(&ku.w)); kf[6]=f.x; kf[7]=f.y;
                f = __half22float2(*reinterpret_cast<__half2*>(&vu.x)); vf[0]=f.x; vf[1]=f.y;
                f = __half22float2(*reinterpret_cast<__half2*>(&vu.y)); vf[2]=f.x; vf[3]=f.y;
                f = __half22float2(*reinterpret_cast<__half2*>(&vu.z)); vf[4]=f.x; vf[5]=f.y;
                f = __half22float2(*reinterpret_cast<__half2*>(&vu.w)); vf[6]=f.x; vf[7]=f.y;
            }
#pragma unroll
            for (int xx = 0; xx < 8; xx++)
#pragma unroll
                for (int yy = 0; yy < 8; yy++) acc[xx][yy] += kf[xx] * vf[yy];
        }
    }

#pragma unroll
    for (int xx = 0; xx < 8; xx++)
#pragma unroll
        for (int yy = 0; yy < 8; yy++) {
            float v_ = acc[xx][yy];
            v_ += __shfl_xor_sync(0xffffffffu, v_, 1);
            v_ += __shfl_xor_sync(0xffffffffu, v_, 2);
            v_ += __shfl_xor_sync(0xffffffffu, v_, 4);
            v_ += __shfl_xor_sync(0xffffffffu, v_, 8);
            acc[xx][yy] = v_;
        }
    if (s == 0) {
        float* dst = g_kvp + (size_t)sp * (B_ * H_ * L_ * 64) +
                     (((size_t)(b * 8 + h) * 12 + l) * 64);
#pragma unroll
        for (int xx = 0; xx < 8; xx++)
#pragma unroll
            for (int yy = 0; yy < 8; yy++) dst[xx * 8 + yy] = acc[xx][yy];
    }
}

__global__ void k2r_reduce() {
    const int i = blockIdx.x * 256 + threadIdx.x;
    const int S = B_ * H_ * L_ * 64;
    if (i >= S) return;
    g_kv[i] = g_kvp[i] + g_kvp[i + S] + g_kvp[i + 2 * S] + g_kvp[i + 3 * S];
}

// ============================================================
// K3 (HMMA+LDSM): y = q_sm@kv + v; yc = Wc@y; fragment epilogue.
// ============================================================
#define KVH_PITCH 552
#define K3_KVH_OFF (64 * P72 * 2)                       // 9216
#define K3_YS_OFF  (K3_KVH_OFF + 12 * KVH_PITCH * 2)    // 9216+13248
#define K3_SMEM    (K3_YS_OFF + 128 * P72 * 2)
__global__ __launch_bounds__(256, 3)
void k3_out(const float* __restrict__ wc, const float* __restrict__ bc,
            const float* __restrict__ weight, const float* __restrict__ bias,
            float* __restrict__ out) {
    extern __shared__ char sm3[];
    __half* sWc = (__half*)sm3;                    // 64 x 72
    __half* kvh = (__half*)(sm3 + K3_KVH_OFF);     // 12 x 552
    __half* ys  = (__half*)(sm3 + K3_YS_OFF);      // 128 x 72

    const int t    = threadIdx.x;
    const int b    = blockIdx.x;
    const int base = blockIdx.y * 128;

    for (int i = t; i < 512; i += 256) {
        const int row = i >> 3, seg = i & 7;
        const float4 f0 = *(const float4*)(wc + row * 64 + seg * 8);
        const float4 f1 = *(const float4*)(wc + row * 64 + seg * 8 + 4);
        uint4 u;
        u.x = h2u(__floats2half2_rn(f0.x, f0.y));
        u.y = h2u(__floats2half2_rn(f0.z, f0.w));
        u.z = h2u(__floats2half2_rn(f1.x, f1.y));
        u.w = h2u(__floats2half2_rn(f1.z, f1.w));
        *(uint4*)&sWc[row * P72 + seg * 8] = u;
    }
    // kv -> kvh [l][h*64+xy]  (g_kv layout is (h*12+l)*64 + xy)
    for (int i = t; i < 3072; i += 256) {
        const int idx = i * 2;
        const float2 f = *(const float2*)(g_kv + (size_t)b * 6144 + idx);
        const int h = idx / 768, r = idx % 768, l = r >> 6, xy = r & 63;
        *(__half2*)&kvh[l * KVH_PITCH + h * 64 + xy] = __floats2half2_rn(f.x, f.y);
    }
    __syncthreads();

    const int lane = t & 31, cg = t >> 5;

    // phase A
#pragma unroll
    for (int i = 0; i < 4; i++) {
        const int pl  = lane + 32 * i;
        const int pos = base + pl;
        const int l   = pos % 12;
        const size_t ib = ((size_t)b * NL_ + pos) * 64 + cg * 8;
        uint4 qr = *(const uint4*)&g_q16[ib];
        uint4 vr = *(const uint4*)&g_v16[ib];
        float q[8], y[8];
        {
            float2 f;
            f = __half22float2(*reinterpret_cast<__half2*>(&qr.x)); q[0]=f.x; q[1]=f.y;
            f = __half22float2(*reinterpret_cast<__half2*>(&qr.y)); q[2]=f.x; q[3]=f.y;
            f = __half22float2(*reinterpret_cast<__half2*>(&qr.z)); q[4]=f.x; q[5]=f.y;
            f = __half22float2(*reinterpret_cast<__half2*>(&qr.w)); q[6]=f.x; q[7]=f.y;
            f = __half22float2(*reinterpret_cast<__half2*>(&vr.x)); y[0]=f.x; y[1]=f.y;
            f = __half22float2(*reinterpret_cast<__half2*>(&vr.y)); y[2]=f.x; y[3]=f.y;
            f = __half22float2(*reinterpret_cast<__half2*>(&vr.z)); y[4]=f.x; y[5]=f.y;
            f = __half22float2(*reinterpret_cast<__half2*>(&vr.w)); y[6]=f.x; y[7]=f.y;
        }
        const __half* kvp = kvh + l * KVH_PITCH + cg * 64;
#pragma unroll
        for (int xx = 0; xx < 8; xx++) {
            uint4 kk = *(const uint4*)(kvp + xx * 8);
            const float qx = q[xx];
            float2 f;
            f = __half22float2(*reinterpret_cast<__half2*>(&kk.x));
            y[0] += qx * f.x; y[1] += qx * f.y;
            f = __half22float2(*reinterpret_cast<__half2*>(&kk.y));
            y[2] += qx * f.x; y[3] += qx * f.y;
            f = __half22float2(*reinterpret_cast<__half2*>(&kk.z));
            y[4] += qx * f.x; y[5] += qx * f.y;
            f = __half22float2(*reinterpret_cast<__half2*>(&kk.w));
            y[6] += qx * f.x; y[7] += qx * f.y;
        }
        uint4 u;
        u.x = h2u(__floats2half2_rn(y[0], y[1]));
        u.y = h2u(__floats2half2_rn(y[2], y[3]));
        u.z = h2u(__floats2half2_rn(y[4], y[5]));
        u.w = h2u(__floats2half2_rn(y[6], y[7]));
        *(uint4*)&ys[pl * P72 + cg * 8] = u;
    }
    __syncthreads();

    // phase B
    const int wid = t >> 5;
    const int g = lane >> 2, q4 = lane & 3;
    const int wm = wid & 3, wn = wid >> 2;

    uint32_t a[4][4];
    {
        const uint32_t abase =
            su(sWc + (wm * 16 + (lane & 15)) * P72 + (lane >> 4) * 8);
#pragma unroll
        for (int kt = 0; kt < 4; kt++)
            LDSM4(a[kt][0], a[kt][1], a[kt][2], a[kt][3], abase + kt * 32);
    }

    float acc[8][4];
#pragma unroll
    for (int nt = 0; nt < 8; nt++)
#pragma unroll
        for (int i = 0; i < 4; i++) acc[nt][i] = 0.f;

    const int brow = lane & 7, bseg = lane >> 3;
#pragma unroll
    for (int nt = 0; nt < 8; nt++) {
        const uint32_t bbase =
            su(ys + (wn * 64 + nt * 8 + brow) * P72 + bseg * 8);
#pragma unroll
        for (int kg = 0; kg < 2; kg++) {
            uint32_t r0, r1, r2, r3;
            LDSM4(r0, r1, r2, r3, bbase + kg * 64);
            mma16816(acc[nt], a[kg * 2],     r0, r1);
            mma16816(acc[nt], a[kg * 2 + 1], r2, r3);
        }
    }

    const int r0 = wm * 16 + g, r1 = r0 + 8;
    const float bc0 = bc[r0], bc1 = bc[r1];
#pragma unroll
    for (int nt = 0; nt < 8; nt++) {
        const int col = base + wn * 64 + nt * 8 + q4 * 2;
        const size_t w0 = (size_t)r0 * NL_ + col;
        const size_t w1 = (size_t)r1 * NL_ + col;
        const float2 wg0 = *(const float2*)(weight + w0);
        const float2 wg1 = *(const float2*)(weight + w1);
        const float2 bi0 = *(const float2*)(bias + w0);
        const float2 bi1 = *(const float2*)(bias + w1);
        float yf;
        float2 o0, o1;
        yf = acc[nt][0] + bc0; yf = yf > 0.f ? yf : 0.f;
        o0.x = yf * wg0.x + bi0.x + yf;
        yf = acc[nt][1] + bc0; yf = yf > 0.f ? yf : 0.f;
        o0.y = yf * wg0.y + bi0.y + yf;
        yf = acc[nt][2] + bc1; yf = yf > 0.f ? yf : 0.f;
        o1.x = yf * wg1.x + bi1.x + yf;
        yf = acc[nt][3] + bc1; yf = yf > 0.f ? yf : 0.f;
        o1.y = yf * wg1.y + bi1.y + yf;
        *(float2*)(out + ((size_t)b * 64) * NL_ + w0) = o0;
        *(float2*)(out + ((size_t)b * 64) * NL_ + w1) = o1;
    }
}

// ============================================================
extern "C" void kernel_launch(void* const* d_in, const int* in_sizes, int n_in,
                              void* d_out, int out_size) {
    const float* x      = (const float*)d_in[0];
    const float* wq     = (const float*)d_in[1];
    const float* bq     = (const float*)d_in[2];
    const float* wv     = (const float*)d_in[3];
    const float* bv     = (const float*)d_in[4];
    const float* wc     = (const float*)d_in[5];
    const float* bc     = (const float*)d_in[6];
    const float* memin  = (const float*)d_in[7];
    const float* weight = (const float*)d_in[8];
    const float* bias   = (const float*)d_in[9];
    // nv1/nv2 unused: row-sum of softmax == 1 -> attn_dyn = v.
    float* out = (float*)d_out;

    cudaFuncSetAttribute(k1_qv,  cudaFuncAttributeMaxDynamicSharedMemorySize, K1_SMEM);
    cudaFuncSetAttribute(k3_out, cudaFuncAttributeMaxDynamicSharedMemorySize, K3_SMEM);

    k0_keysm<<<(H_ * L_ * N_ + 255) / 256, 256>>>(memin);

    dim3 g1(NL_ / 128, B_);
    k1_qv<<<g1, 256, K1_SMEM>>>(x, wq, bq, wv, bv);

    dim3 g2(H_, B_, 4);
    k2_kv<<<g2, 192>>>();
    k2r_reduce<<<(B_ * H_ * L_ * 64 + 255) / 256, 256>>>();

    dim3 g3(B_, NL_ / 128);
    k3_out<<<g3, 256, K3_SMEM>>>(wc, bc, weight, bias, out);
}

// round 8
// speedup vs baseline: 2.6548x; 1.0715x over previous
#include <cuda_runtime.h>
#include <cuda_fp16.h>
#include <math.h>
#include <stdint.h>

#define B_ 32
#define D_ 64
#define H_ 8
#define N_ 4096
#define L_ 12
#define DK_ 8
#define NL_ 49152
#define SCALE 0.3535533905932738f

// ---- scratch ----
__device__ __half g_q16[(size_t)B_ * NL_ * 64];
__device__ __half g_v16[(size_t)B_ * NL_ * 64];
__device__ __half g_keysm16[(size_t)H_ * L_ * N_ * DK_];
__device__ float  g_kv[B_ * H_ * L_ * DK_ * DK_];
__device__ float  g_kvp[4 * B_ * H_ * L_ * DK_ * DK_];

__device__ __forceinline__ void mma16816(float* c, const uint32_t* a,
                                         uint32_t b0, uint32_t b1) {
    asm volatile(
        "mma.sync.aligned.m16n8k16.row.col.f32.f16.f16.f32 "
        "{%0,%1,%2,%3}, {%4,%5,%6,%7}, {%8,%9}, {%0,%1,%2,%3};\n"
        : "+f"(c[0]), "+f"(c[1]), "+f"(c[2]), "+f"(c[3])
        : "r"(a[0]), "r"(a[1]), "r"(a[2]), "r"(a[3]), "r"(b0), "r"(b1));
}

__device__ __forceinline__ uint32_t su(const void* p) {
    return (uint32_t)__cvta_generic_to_shared(p);
}

#define LDSM4(r0, r1, r2, r3, addr)                                        \
    asm volatile("ldmatrix.sync.aligned.m8n8.x4.shared.b16 {%0,%1,%2,%3}, [%4];" \
                 : "=r"(r0), "=r"(r1), "=r"(r2), "=r"(r3) : "r"(addr))

#define STSM4T(addr, r0, r1, r2, r3)                                       \
    asm volatile("stmatrix.sync.aligned.m8n8.x4.trans.shared.b16 [%0], {%1,%2,%3,%4};" \
                 :: "r"(addr), "r"(r0), "r"(r1), "r"(r2), "r"(r3))

__device__ __forceinline__ uint32_t h2u(__half2 h) {
    return *reinterpret_cast<uint32_t*>(&h);
}

// ============================================================
// K0: key_sm = softmax(memory * scale, axis=-1) -> fp16
// ============================================================
__global__ void k0_keysm(const float* __restrict__ memin) {
    int i = blockIdx.x * blockDim.x + threadIdx.x;
    if (i >= H_ * L_ * N_) return;
    const float4 f0 = ((const float4*)memin)[(size_t)i * 2];
    const float4 f1 = ((const float4*)memin)[(size_t)i * 2 + 1];
    float v[8] = {f0.x, f0.y, f0.z, f0.w, f1.x, f1.y, f1.z, f1.w};
    float m = -1e30f;
#pragma unroll
    for (int k = 0; k < 8; k++) { v[k] *= SCALE; m = fmaxf(m, v[k]); }
    float s = 0.f;
#pragma unroll
    for (int k = 0; k < 8; k++) { v[k] = __expf(v[k] - m); s += v[k]; }
    const float inv = 1.f / s;
    uint4 u;
    u.x = h2u(__floats2half2_rn(v[0] * inv, v[1] * inv));
    u.y = h2u(__floats2half2_rn(v[2] * inv, v[3] * inv));
    u.z = h2u(__floats2half2_rn(v[4] * inv, v[5] * inv));
    u.w = h2u(__floats2half2_rn(v[6] * inv, v[7] * inv));
    ((uint4*)g_keysm16)[i] = u;
}

// ============================================================
// K1 (HMMA+LDSM+STSM): [q;v](128 x 128) = [Wq;Wv] @ x
// Fragments stored via stmatrix.trans into sQV[pos][ch] (pitch 136).
// ============================================================
#define P72 72
#define QVP 136
#define K1_XS_OFF  (128 * P72 * 2)
#define K1_SQV_OFF (K1_XS_OFF + 128 * P72 * 2)
#define K1_SMEM    (K1_SQV_OFF + 128 * QVP * 2)
__global__ __launch_bounds__(256, 3)
void k1_qv(const float* __restrict__ x,  const float* __restrict__ wq,
           const float* __restrict__ bq, const float* __restrict__ wv,
           const float* __restrict__ bv) {
    extern __shared__ char sm1[];
    __half* sW  = (__half*)sm1;                    // 128 x 72
    __half* xs  = (__half*)(sm1 + K1_XS_OFF);      // 128 x 72
    __half* sQV = (__half*)(sm1 + K1_SQV_OFF);     // 128 x 136  [pos][ch]

    const int t    = threadIdx.x;
    const int b    = blockIdx.y;
    const int base = blockIdx.x * 128;

    for (int i = t; i < 512; i += 256) {
        const int row = i >> 3, seg = i & 7;
        const float4 f0 = *(const float4*)(wq + row * 64 + seg * 8);
        const float4 f1 = *(const float4*)(wq + row * 64 + seg * 8 + 4);
        uint4 u;
        u.x = h2u(__floats2half2_rn(f0.x, f0.y));
        u.y = h2u(__floats2half2_rn(f0.z, f0.w));
        u.z = h2u(__floats2half2_rn(f1.x, f1.y));
        u.w = h2u(__floats2half2_rn(f1.z, f1.w));
        *(uint4*)&sW[row * P72 + seg * 8] = u;
        const float4 g0 = *(const float4*)(wv + row * 64 + seg * 8);
        const float4 g1 = *(const float4*)(wv + row * 64 + seg * 8 + 4);
        u.x = h2u(__floats2half2_rn(g0.x, g0.y));
        u.y = h2u(__floats2half2_rn(g0.z, g0.w));
        u.z = h2u(__floats2half2_rn(g1.x, g1.y));
        u.w = h2u(__floats2half2_rn(g1.z, g1.w));
        *(uint4*)&sW[(64 + row) * P72 + seg * 8] = u;
    }
    {
        const int pos = t & 127;
        const int d0  = (t >> 7) * 32;
        const float* xb = x + (size_t)b * D_ * NL_ + base + pos;
        uint32_t pk[16];
#pragma unroll 4
        for (int dd = 0; dd < 32; dd += 2) {
            float x0 = xb[(size_t)(d0 + dd) * NL_];
            float x1 = xb[(size_t)(d0 + dd + 1) * NL_];
            pk[dd >> 1] = h2u(__floats2half2_rn(x0, x1));
        }
        uint4* dst = (uint4*)&xs[pos * P72 + d0];
#pragma unroll
        for (int s = 0; s < 4; s++)
            dst[s] = make_uint4(pk[4 * s], pk[4 * s + 1], pk[4 * s + 2], pk[4 * s + 3]);
    }
    __syncthreads();

    const int wid = t >> 5, lane = t & 31;

    uint32_t a[4][4];
    {
        const uint32_t abase =
            su(sW + (wid * 16 + (lane & 15)) * P72 + (lane >> 4) * 8);
#pragma unroll
        for (int kt = 0; kt < 4; kt++)
            LDSM4(a[kt][0], a[kt][1], a[kt][2], a[kt][3], abase + kt * 32);
    }

    // stmatrix base: matrix = lane>>3; mats 0,1 -> pos tile 0 / ch {0,+8};
    // mats 2,3 -> pos tile +8 / ch {0,+8}
    const int mat = lane >> 3, mrow = lane & 7;
    const uint32_t stbase =
        su(sQV + ((mat >> 1) * 8 + mrow) * QVP + wid * 16 + (mat & 1) * 8);

    const int brow = lane & 7, bseg = lane >> 3;
#pragma unroll
    for (int pass = 0; pass < 2; pass++) {
        float acc[8][4];
#pragma unroll
        for (int nt = 0; nt < 8; nt++)
#pragma unroll
            for (int i = 0; i < 4; i++) acc[nt][i] = 0.f;

#pragma unroll
        for (int nt = 0; nt < 8; nt++) {
            const int ntg = pass * 8 + nt;
            const uint32_t bbase = su(xs + (ntg * 8 + brow) * P72 + bseg * 8);
#pragma unroll
            for (int kg = 0; kg < 2; kg++) {
                uint32_t r0, r1, r2, r3;
                LDSM4(r0, r1, r2, r3, bbase + kg * 64);
                mma16816(acc[nt], a[kg * 2],     r0, r1);
                mma16816(acc[nt], a[kg * 2 + 1], r2, r3);
            }
        }
        // fragments -> sQV via stmatrix.trans (2 nt per store)
#pragma unroll
        for (int j = 0; j < 4; j++) {
            const int nt0 = 2 * j;
            const uint32_t addr = stbase + (uint32_t)((pass * 8 + nt0) * 8 * QVP * 2);
            const uint32_t r0 = h2u(__floats2half2_rn(acc[nt0][0],     acc[nt0][1]));
            const uint32_t r1 = h2u(__floats2half2_rn(acc[nt0][2],     acc[nt0][3]));
            const uint32_t r2 = h2u(__floats2half2_rn(acc[nt0 + 1][0], acc[nt0 + 1][1]));
            const uint32_t r3 = h2u(__floats2half2_rn(acc[nt0 + 1][2], acc[nt0 + 1][3]));
            STSM4T(addr, r0, r1, r2, r3);
        }
    }
    __syncthreads();

    // epilogue: per pos, q/v channel groups are contiguous -> LDS.128
    const int cg = t >> 5;
    float bqv[8], bvv[8];
#pragma unroll
    for (int j = 0; j < 8; j++) { bqv[j] = bq[cg * 8 + j]; bvv[j] = bv[cg * 8 + j]; }

#pragma unroll
    for (int i = 0; i < 4; i++) {
        const int pos = lane + 32 * i;
        const __half* row = sQV + pos * QVP;
        uint4 qraw = *(const uint4*)(row + cg * 8);
        uint4 vraw = *(const uint4*)(row + 64 + cg * 8);
        float q[8], vv[8];
        {
            float2 f;
            f = __half22float2(*reinterpret_cast<__half2*>(&qraw.x)); q[0]=f.x; q[1]=f.y;
            f = __half22float2(*reinterpret_cast<__half2*>(&qraw.y)); q[2]=f.x; q[3]=f.y;
            f = __half22float2(*reinterpret_cast<__half2*>(&qraw.z)); q[4]=f.x; q[5]=f.y;
            f = __half22float2(*reinterpret_cast<__half2*>(&qraw.w)); q[6]=f.x; q[7]=f.y;
            f = __half22float2(*reinterpret_cast<__half2*>(&vraw.x)); vv[0]=f.x; vv[1]=f.y;
            f = __half22float2(*reinterpret_cast<__half2*>(&vraw.y)); vv[2]=f.x; vv[3]=f.y;
            f = __half22float2(*reinterpret_cast<__half2*>(&vraw.z)); vv[4]=f.x; vv[5]=f.y;
            f = __half22float2(*reinterpret_cast<__half2*>(&vraw.w)); vv[6]=f.x; vv[7]=f.y;
        }
        float m = 0.f;
#pragma unroll
        for (int j = 0; j < 8; j++) {
            float qq = q[j] + bqv[j];
            qq = qq > 0.f ? qq : 0.f;
            q[j] = qq * SCALE;
            m = fmaxf(m, q[j]);
        }
        float s = 0.f;
#pragma unroll
        for (int j = 0; j < 8; j++) { q[j] = __expf(q[j] - m); s += q[j]; }
        const float inv = 1.f / s;

        uint4 qu, vu;
        qu.x = h2u(__floats2half2_rn(q[0] * inv, q[1] * inv));
        qu.y = h2u(__floats2half2_rn(q[2] * inv, q[3] * inv));
        qu.z = h2u(__floats2half2_rn(q[4] * inv, q[5] * inv));
        qu.w = h2u(__floats2half2_rn(q[6] * inv, q[7] * inv));
#pragma unroll
        for (int j = 0; j < 8; j++) {
            float f = vv[j] + bvv[j];
            vv[j] = f > 0.f ? f : 0.f;
        }
        vu.x = h2u(__floats2half2_rn(vv[0], vv[1]));
        vu.y = h2u(__floats2half2_rn(vv[2], vv[3]));
        vu.z = h2u(__floats2half2_rn(vv[4], vv[5]));
        vu.w = h2u(__floats2half2_rn(vv[6], vv[7]));

        const size_t ob = ((size_t)b * NL_ + base + pos) * 64 + cg * 8;
        *(uint4*)&g_q16[ob] = qu;
        *(uint4*)&g_v16[ob] = vu;
    }
}

// ============================================================
// K2: split-K partial kv sums; fp16 tiles staged as uint4.
// ============================================================
#define K2_NCH 64
__global__ __launch_bounds__(192, 3)
void k2_kv() {
    __shared__ __half sK[12][K2_NCH][8];
    __shared__ __half sV[12][K2_NCH][8];

    const int t = threadIdx.x;
    const int h = blockIdx.x;
    const int b = blockIdx.y;
    const int sp = blockIdx.z;
    const int s = t & 15;
    const int l = t >> 4;

    float acc[8][8];
#pragma unroll
    for (int xx = 0; xx < 8; xx++)
#pragma unroll
        for (int yy = 0; yy < 8; yy++) acc[xx][yy] = 0.f;

    const int nlo = sp * (N_ / 4), nhi = nlo + N_ / 4;
    for (int n0 = nlo; n0 < nhi; n0 += K2_NCH) {
        __syncthreads();
#pragma unroll
        for (int i = t; i < 12 * K2_NCH; i += 192) {
            const int ll = i >> 6, nn = i & 63;
            *(uint4*)&sK[ll][nn][0] =
                *(const uint4*)&g_keysm16[((size_t)(h * 12 + ll) * N_ + n0 + nn) * 8];
        }
#pragma unroll
        for (int i = t; i < 12 * K2_NCH; i += 192) {
            const int ll = i % 12, nn = i / 12;
            const int pos = (n0 + nn) * 12 + ll;
            *(uint4*)&sV[ll][nn][0] =
                *(const uint4*)&g_v16[((size_t)b * NL_ + pos) * 64 + h * 8];
        }
        __syncthreads();

#pragma unroll
        for (int p = 0; p < 4; p++) {
            const int nn = s + 16 * p;
            float kf[8], vf[8];
            uint4 ku = *(const uint4*)&sK[l][nn][0];
            uint4 vu = *(const uint4*)&sV[l][nn][0];
            {
                float2 f;
                f = __half22float2(*reinterpret_cast<__half2*>(&ku.x)); kf[0]=f.x; kf[1]=f.y;
                f = __half22float2(*reinterpret_cast<__half2*>(&ku.y)); kf[2]=f.x; kf[3]=f.y;
                f = __half22float2(*reinterpret_cast<__half2*>(&ku.z)); kf[4]=f.x; kf[5]=f.y;
                f = __half22float2(*reinterpret_cast<__half2*>(&ku.w)); kf[6]=f.x; kf[7]=f.y;
                f = __half22float2(*reinterpret_cast<__half2*>(&vu.x)); vf[0]=f.x; vf[1]=f.y;
                f = __half22float2(*reinterpret_cast<__half2*>(&vu.y)); vf[2]=f.x; vf[3]=f.y;
                f = __half22float2(*reinterpret_cast<__half2*>(&vu.z)); vf[4]=f.x; vf[5]=f.y;
                f = __half22float2(*reinterpret_cast<__half2*>(&vu.w)); vf[6]=f.x; vf[7]=f.y;
            }
#pragma unroll
            for (int xx = 0; xx < 8; xx++)
#pragma unroll
                for (int yy = 0; yy < 8; yy++) acc[xx][yy] += kf[xx] * vf[yy];
        }
    }

#pragma unroll
    for (int xx = 0; xx < 8; xx++)
#pragma unroll
        for (int yy = 0; yy < 8; yy++) {
            float v_ = acc[xx][yy];
            v_ += __shfl_xor_sync(0xffffffffu, v_, 1);
            v_ += __shfl_xor_sync(0xffffffffu, v_, 2);
            v_ += __shfl_xor_sync(0xffffffffu, v_, 4);
            v_ += __shfl_xor_sync(0xffffffffu, v_, 8);
            acc[xx][yy] = v_;
        }
    if (s == 0) {
        float* dst = g_kvp + (size_t)sp * (B_ * H_ * L_ * 64) +
                     (((size_t)(b * 8 + h) * 12 + l) * 64);
#pragma unroll
        for (int xx = 0; xx < 8; xx++)
#pragma unroll
            for (int yy = 0; yy < 8; yy++) dst[xx * 8 + yy] = acc[xx][yy];
    }
}

__global__ void k2r_reduce() {
    const int i = blockIdx.x * 256 + threadIdx.x;
    const int S = B_ * H_ * L_ * 64;
    if (i >= S) return;
    g_kv[i] = g_kvp[i] + g_kvp[i + S] + g_kvp[i + 2 * S] + g_kvp[i + 3 * S];
}

// ============================================================
// K3 (HMMA+LDSM, 2 tiles/block): y = q_sm@kv + v; yc = Wc@y.
// ============================================================
#define KVH_PITCH 552
#define K3_KVH_OFF (64 * P72 * 2)                       // 9216
#define K3_YS_OFF  (K3_KVH_OFF + 12 * KVH_PITCH * 2)    // 9216+13248
#define K3_SMEM    (K3_YS_OFF + 128 * P72 * 2)
__global__ __launch_bounds__(256, 3)
void k3_out(const float* __restrict__ wc, const float* __restrict__ bc,
            const float* __restrict__ weight, const float* __restrict__ bias,
            float* __restrict__ out) {
    extern __shared__ char sm3[];
    __half* sWc = (__half*)sm3;                    // 64 x 72
    __half* kvh = (__half*)(sm3 + K3_KVH_OFF);     // 12 x 552
    __half* ys  = (__half*)(sm3 + K3_YS_OFF);      // 128 x 72

    const int t = threadIdx.x;
    const int b = blockIdx.x;

    for (int i = t; i < 512; i += 256) {
        const int row = i >> 3, seg = i & 7;
        const float4 f0 = *(const float4*)(wc + row * 64 + seg * 8);
        const float4 f1 = *(const float4*)(wc + row * 64 + seg * 8 + 4);
        uint4 u;
        u.x = h2u(__floats2half2_rn(f0.x, f0.y));
        u.y = h2u(__floats2half2_rn(f0.z, f0.w));
        u.z = h2u(__floats2half2_rn(f1.x, f1.y));
        u.w = h2u(__floats2half2_rn(f1.z, f1.w));
        *(uint4*)&sWc[row * P72 + seg * 8] = u;
    }
    // kv -> kvh [l][h*64+xy]  (g_kv layout is (h*12+l)*64 + xy)
    for (int i = t; i < 3072; i += 256) {
        const int idx = i * 2;
        const float2 f = *(const float2*)(g_kv + (size_t)b * 6144 + idx);
        const int h = idx / 768, r = idx % 768, l = r >> 6, xy = r & 63;
        *(__half2*)&kvh[l * KVH_PITCH + h * 64 + xy] = __floats2half2_rn(f.x, f.y);
    }
    __syncthreads();

    const int lane = t & 31, cg = t >> 5;
    const int wid = t >> 5;
    const int g = lane >> 2, q4 = lane & 3;
    const int wm = wid & 3, wn = wid >> 2;

    // A fragments (Wc) once
    uint32_t a[4][4];
    {
        const uint32_t abase =
            su(sWc + (wm * 16 + (lane & 15)) * P72 + (lane >> 4) * 8);
#pragma unroll
        for (int kt = 0; kt < 4; kt++)
            LDSM4(a[kt][0], a[kt][1], a[kt][2], a[kt][3], abase + kt * 32);
    }

    const int r0_ = wm * 16 + g, r1_ = r0_ + 8;
    const float bc0 = bc[r0_], bc1 = bc[r1_];
    const int brow = lane & 7, bseg = lane >> 3;

    for (int tile = 0; tile < 2; tile++) {
        const int base = blockIdx.y * 256 + tile * 128;

        // phase A: y = v + q_sm @ kv -> ys[pos][ch]
#pragma unroll
        for (int i = 0; i < 4; i++) {
            const int pl  = lane + 32 * i;
            const int pos = base + pl;
            const int l   = pos % 12;
            const size_t ib = ((size_t)b * NL_ + pos) * 64 + cg * 8;
            uint4 qr = *(const uint4*)&g_q16[ib];
            uint4 vr = *(const uint4*)&g_v16[ib];
            float q[8], y[8];
            {
                float2 f;
                f = __half22float2(*reinterpret_cast<__half2*>(&qr.x)); q[0]=f.x; q[1]=f.y;
                f = __half22float2(*reinterpret_cast<__half2*>(&qr.y)); q[2]=f.x; q[3]=f.y;
                f = __half22float2(*reinterpret_cast<__half2*>(&qr.z)); q[4]=f.x; q[5]=f.y;
                f = __half22float2(*reinterpret_cast<__half2*>(&qr.w)); q[6]=f.x; q[7]=f.y;
                f = __half22float2(*reinterpret_cast<__half2*>(&vr.x)); y[0]=f.x; y[1]=f.y;
                f = __half22float2(*reinterpret_cast<__half2*>(&vr.y)); y[2]=f.x; y[3]=f.y;
                f = __half22float2(*reinterpret_cast<__half2*>(&vr.z)); y[4]=f.x; y[5]=f.y;
                f = __half22float2(*reinterpret_cast<__half2*>(&vr.w)); y[6]=f.x; y[7]=f.y;
            }
            const __half* kvp = kvh + l * KVH_PITCH + cg * 64;
#pragma unroll
            for (int xx = 0; xx < 8; xx++) {
                uint4 kk = *(const uint4*)(kvp + xx * 8);
                const float qx = q[xx];
                float2 f;
                f = __half22float2(*reinterpret_cast<__half2*>(&kk.x));
                y[0] += qx * f.x; y[1] += qx * f.y;
                f = __half22float2(*reinterpret_cast<__half2*>(&kk.y));
                y[2] += qx * f.x; y[3] += qx * f.y;
                f = __half22float2(*reinterpret_cast<__half2*>(&kk.z));
                y[4] += qx * f.x; y[5] += qx * f.y;
                f = __half22float2(*reinterpret_cast<__half2*>(&kk.w));
                y[6] += qx * f.x; y[7] += qx * f.y;
            }
            uint4 u;
            u.x = h2u(__floats2half2_rn(y[0], y[1]));
            u.y = h2u(__floats2half2_rn(y[2], y[3]));
            u.z = h2u(__floats2half2_rn(y[4], y[5]));
            u.w = h2u(__floats2half2_rn(y[6], y[7]));
            *(uint4*)&ys[pl * P72 + cg * 8] = u;
        }
        __syncthreads();

        // phase B: HMMA via LDSM
        float acc[8][4];
#pragma unroll
        for (int nt = 0; nt < 8; nt++)
#pragma unroll
            for (int i = 0; i < 4; i++) acc[nt][i] = 0.f;

#pragma unroll
        for (int nt = 0; nt < 8; nt++) {
            const uint32_t bbase =
                su(ys + (wn * 64 + nt * 8 + brow) * P72 + bseg * 8);
#pragma unroll
            for (int kg = 0; kg < 2; kg++) {
                uint32_t r0, r1, r2, r3;
                LDSM4(r0, r1, r2, r3, bbase + kg * 64);
                mma16816(acc[nt], a[kg * 2],     r0, r1);
                mma16816(acc[nt], a[kg * 2 + 1], r2, r3);
            }
        }

        // fragment epilogue
#pragma unroll
        for (int nt = 0; nt < 8; nt++) {
            const int col = base + wn * 64 + nt * 8 + q4 * 2;
            const size_t w0 = (size_t)r0_ * NL_ + col;
            const size_t w1 = (size_t)r1_ * NL_ + col;
            const float2 wg0 = *(const float2*)(weight + w0);
            const float2 wg1 = *(const float2*)(weight + w1);
            const float2 bi0 = *(const float2*)(bias + w0);
            const float2 bi1 = *(const float2*)(bias + w1);
            float yf;
            float2 o0, o1;
            yf = acc[nt][0] + bc0; yf = yf > 0.f ? yf : 0.f;
            o0.x = yf * wg0.x + bi0.x + yf;
            yf = acc[nt][1] + bc0; yf = yf > 0.f ? yf : 0.f;
            o0.y = yf * wg0.y + bi0.y + yf;
            yf = acc[nt][2] + bc1; yf = yf > 0.f ? yf : 0.f;
            o1.x = yf * wg1.x + bi1.x + yf;
            yf = acc[nt][3] + bc1; yf = yf > 0.f ? yf : 0.f;
            o1.y = yf * wg1.y + bi1.y + yf;
            *(float2*)(out + ((size_t)b * 64) * NL_ + w0) = o0;
            *(float2*)(out + ((size_t)b * 64) * NL_ + w1) = o1;
        }
        __syncthreads();   // ys reads complete before next tile's writes
    }
}

// ============================================================
extern "C" void kernel_launch(void* const* d_in, const int* in_sizes, int n_in,
                              void* d_out, int out_size) {
    const float* x      = (const float*)d_in[0];
    const float* wq     = (const float*)d_in[1];
    const float* bq     = (const float*)d_in[2];
    const float* wv     = (const float*)d_in[3];
    const float* bv     = (const float*)d_in[4];
    const float* wc     = (const float*)d_in[5];
    const float* bc     = (const float*)d_in[6];
    const float* memin  = (const float*)d_in[7];
    const float* weight = (const float*)d_in[8];
    const float* bias   = (const float*)d_in[9];
    // nv1/nv2 unused: row-sum of softmax == 1 -> attn_dyn = v.
    float* out = (float*)d_out;

    cudaFuncSetAttribute(k1_qv,  cudaFuncAttributeMaxDynamicSharedMemorySize, K1_SMEM);
    cudaFuncSetAttribute(k3_out, cudaFuncAttributeMaxDynamicSharedMemorySize, K3_SMEM);

    k0_keysm<<<(H_ * L_ * N_ + 255) / 256, 256>>>(memin);

    dim3 g1(NL_ / 128, B_);
    k1_qv<<<g1, 256, K1_SMEM>>>(x, wq, bq, wv, bv);

    dim3 g2(H_, B_, 4);
    k2_kv<<<g2, 192>>>();
    k2r_reduce<<<(B_ * H_ * L_ * 64 + 255) / 256, 256>>>();

    dim3 g3(B_, NL_ / 256);
    k3_out<<<g3, 256, K3_SMEM>>>(wc, bc, weight, bias, out);
}